// round 2
// baseline (speedup 1.0000x reference)
#include <cuda_runtime.h>
#include <math.h>

#define NPIX   542
#define NPIX2  (NPIX*NPIX)
#define NIMG   16
#define M2048  2048
#define LOGM   11
#define KH     31
#define NF     8
#define NBATCH 8
#define INV542 (1.0f/542.0f)

// ---------------- scratch (static device globals; no allocation) -------------
__device__ float2 g_A[NIMG*NPIX2];        // working images (packed complex)
__device__ float2 g_B[NIMG*NPIX2];        // spectra / blurred
__device__ float2 g_Kotf[NBATCH*NPIX2];   // per-batch blur OTF
__device__ float  g_Gsum[3*NPIX2];        // sum_f |Dg|^2 per channel
__device__ float2 g_T[NBATCH*NPIX*KH];    // OTF intermediate
__device__ float  g_v[NBATCH*2*NPIX];     // edgetaper 1D windows
__device__ float2 g_Wtab[M2048/2];        // FFT-2048 twiddles
__device__ float2 g_Achirp[NPIX];         // Bluestein chirp a[n]=e^{-i pi n^2/542}
__device__ float2 g_E542[NPIX];           // e^{-2 pi i t/542}
__device__ float2 g_Bhat[M2048];          // FFT(chirp b) / 2048

__device__ __forceinline__ float2 cmul(float2 a, float2 b) {
  return make_float2(a.x*b.x - a.y*b.y, a.x*b.y + a.y*b.x);
}

// ---------------- radix-2 FFT-2048 in shared memory --------------------------
__device__ void fft2048(float2* s, int tid, bool inv) {
  __syncthreads();
#pragma unroll
  for (int kk = 0; kk < 8; kk++) {
    int n = tid + (kk << 8);
    int r = __brev(n) >> (32 - LOGM);
    if (r > n) { float2 t = s[n]; s[n] = s[r]; s[r] = t; }
  }
  __syncthreads();
#pragma unroll
  for (int st = 1; st <= LOGM; st++) {
    int half = 1 << (st - 1);
#pragma unroll
    for (int kk = 0; kk < 4; kk++) {
      int idx = tid + (kk << 8);
      int pos = idx & (half - 1);
      int i0  = ((idx ^ pos) << 1) | pos;
      float2 w = g_Wtab[pos << (LOGM - st)];
      if (inv) w.y = -w.y;
      float2 u = s[i0];
      float2 t = cmul(w, s[i0 + half]);
      s[i0]        = make_float2(u.x + t.x, u.y + t.y);
      s[i0 + half] = make_float2(u.x - t.x, u.y - t.y);
    }
    __syncthreads();
  }
}

// Bluestein convolution core: s holds chirped input (zero padded); after call,
// s[k]*Achirp[k] is the forward DFT-542 of the original sequence.
__device__ void conv_core(float2* s, int tid) {
  fft2048(s, tid, false);
#pragma unroll
  for (int kk = 0; kk < 8; kk++) {
    int n = tid + (kk << 8);
    s[n] = cmul(s[n], g_Bhat[n]);
  }
  fft2048(s, tid, true);   // unnormalized inverse (1/2048 folded into Bhat)
}

// ---------------- table init -------------------------------------------------
__global__ void init_tables() {
  int t = blockIdx.x * blockDim.x + threadIdx.x;
  if (t < M2048/2) {
    double a = -(M_PI / (M2048/2)) * (double)t;   // -2*pi*t/2048
    g_Wtab[t] = make_float2((float)cos(a), (float)sin(a));
  }
  if (t < NPIX) {
    long long m = ((long long)t * t) % (2*NPIX);
    double a = -(M_PI / (double)NPIX) * (double)m;
    g_Achirp[t] = make_float2((float)cos(a), (float)sin(a));
    double a2 = -(2.0 * M_PI / (double)NPIX) * (double)t;
    g_E542[t] = make_float2((float)cos(a2), (float)sin(a2));
  }
}

__global__ void init_bhat() {
  __shared__ float2 s[M2048];
  int tid = threadIdx.x;
#pragma unroll
  for (int kk = 0; kk < 8; kk++) {
    int n = tid + (kk << 8);
    float2 v = make_float2(0.f, 0.f);
    if (n < NPIX)            { float2 a = g_Achirp[n];         v = make_float2(a.x, -a.y); }
    else if (n > M2048-NPIX) { float2 a = g_Achirp[M2048 - n]; v = make_float2(a.x, -a.y); }
    s[n] = v;
  }
  fft2048(s, tid, false);
#pragma unroll
  for (int kk = 0; kk < 8; kk++) {
    int n = tid + (kk << 8);
    g_Bhat[n] = make_float2(s[n].x * (1.f/M2048), s[n].y * (1.f/M2048));
  }
}

// ---------------- edgetaper alpha windows (direct autocorrelation) ------------
__global__ void compute_v(const float* __restrict__ k) {
  int b = blockIdx.x, tid = threadIdx.x;           // 32 threads
  __shared__ float p0[KH], p1[KH], r0a[KH], r1a[KH];
  if (tid < KH) {
    float s0 = 0.f, s1 = 0.f;
    for (int j = 0; j < KH; j++) {
      s0 += k[b*KH*KH + tid*KH + j];   // sum over axis 1 -> proj over rows
      s1 += k[b*KH*KH + j*KH + tid];   // sum over axis 0 -> proj over cols
    }
    p0[tid] = s0; p1[tid] = s1;
  }
  __syncthreads();
  if (tid < KH) {
    float a0 = 0.f, a1 = 0.f;
    for (int m = 0; m + tid < KH; m++) { a0 += p0[m]*p0[m+tid]; a1 += p1[m]*p1[m+tid]; }
    r0a[tid] = a0; r1a[tid] = a1;
  }
  __syncthreads();
  float inv0 = 1.f / r0a[0], inv1 = 1.f / r1a[0];
  for (int n = tid; n < NPIX; n += 32) {
    float z0 = 0.f, z1 = 0.f;
    if (n <= KH-1)                         { z0 = r0a[n];            z1 = r1a[n]; }
    else if (n >= NPIX-KH && n <= NPIX-2)  { z0 = r0a[(NPIX-1) - n]; z1 = r1a[(NPIX-1) - n]; }
    else if (n == NPIX-1)                  { z0 = r0a[0];            z1 = r1a[0]; }
    g_v[(b*2+0)*NPIX + n] = 1.f - z0 * inv0;
    g_v[(b*2+1)*NPIX + n] = 1.f - z1 * inv1;
  }
}

// ---------------- direct-DFT OTFs --------------------------------------------
__global__ void kotf_pass1(const float* __restrict__ k) {
  int u = blockIdx.x, b = blockIdx.y, j = threadIdx.x;
  if (j >= KH) return;
  float2 acc = make_float2(0.f, 0.f);
  for (int i = 0; i < KH; i++) {
    int m = u * (i - 15);
    int idx = m % NPIX; if (idx < 0) idx += NPIX;
    float2 e = g_E542[idx];
    float  w = k[b*KH*KH + i*KH + j];
    acc.x += w*e.x; acc.y += w*e.y;
  }
  g_T[(b*NPIX + u)*KH + j] = acc;
}

__global__ void kotf_pass2() {
  int u = blockIdx.x, b = blockIdx.y, tid = threadIdx.x;
  __shared__ float2 Ts[KH];
  if (tid < KH) Ts[tid] = g_T[(b*NPIX + u)*KH + tid];
  __syncthreads();
  for (int v = tid; v < NPIX; v += blockDim.x) {
    float2 acc = make_float2(0.f, 0.f);
    for (int j = 0; j < KH; j++) {
      int m = v * (j - 15);
      int idx = m % NPIX; if (idx < 0) idx += NPIX;
      float2 e = g_E542[idx], t = Ts[j];
      acc.x += t.x*e.x - t.y*e.y;
      acc.y += t.x*e.y + t.y*e.x;
    }
    g_Kotf[(b*NPIX + u)*NPIX + v] = acc;
  }
}

__global__ void gsum_kernel(const float* __restrict__ filt) {
  int u = blockIdx.x, c = blockIdx.y, tid = threadIdx.x;
  __shared__ float f[NF*9];
  if (tid < NF*9) { int ff = tid/9, t = tid%9; f[tid] = filt[(ff*3 + c)*9 + t]; }
  __syncthreads();
  for (int v = tid; v < NPIX; v += blockDim.x) {
    float sum = 0.f;
    for (int ff = 0; ff < NF; ff++) {
      float ar = 0.f, ai = 0.f;
#pragma unroll
      for (int t = 0; t < 9; t++) {
        int i = t/3, j = t%3;
        int sgn = u*(i-1) + v*(j-1);
        int idx = sgn % NPIX; if (idx < 0) idx += NPIX;
        float2 e = g_E542[idx]; float w = f[ff*9 + t];
        ar += w*e.x; ai += w*e.y;
      }
      sum += ar*ar + ai*ai;
    }
    g_Gsum[(c*NPIX + u)*NPIX + v] = sum;
  }
}

// ---------------- pad (edge replicate) + channel pack ------------------------
__global__ void pad_pack(const float* __restrict__ y) {
  int total = NIMG*NPIX2;
  for (int n = blockIdx.x*blockDim.x + threadIdx.x; n < total; n += gridDim.x*blockDim.x) {
    int im = n / NPIX2, rem = n % NPIX2;
    int i = rem / NPIX, j = rem % NPIX;
    int b = im >> 1, p = im & 1;
    int yi = min(max(i - 15, 0), 511), yj = min(max(j - 15, 0), 511);
    const float* yb = y + (size_t)b * 3 * 262144;
    float2 v;
    if (p == 0) v = make_float2(yb[yi*512 + yj], yb[262144 + yi*512 + yj]);
    else        v = make_float2(yb[2*262144 + yi*512 + yj], 0.f);
    g_A[n] = v;
  }
}

// ---------------- FFT pass kernels -------------------------------------------
__global__ void rowfft_fwd() {   // A -> B, forward DFT along rows
  __shared__ float2 s[M2048];
  int row = blockIdx.x, im = blockIdx.y, tid = threadIdx.x;
  size_t base = ((size_t)im*NPIX + row) * NPIX;
#pragma unroll
  for (int kk = 0; kk < 8; kk++) {
    int n = tid + (kk << 8);
    float2 v = make_float2(0.f, 0.f);
    if (n < NPIX) v = cmul(g_A[base + n], g_Achirp[n]);
    s[n] = v;
  }
  conv_core(s, tid);
#pragma unroll
  for (int kk = 0; kk < 3; kk++) {
    int n = tid + (kk << 8);
    if (n < NPIX) g_B[base + n] = cmul(s[n], g_Achirp[n]);
  }
}

// fused: forward col DFT + OTF multiply + inverse col DFT, in-place on B
__global__ void colfft_otf() {
  __shared__ float2 s[M2048];
  __shared__ float2 spec[NPIX];
  int col = blockIdx.x, im = blockIdx.y, tid = threadIdx.x, b = im >> 1;
  size_t base = (size_t)im*NPIX2 + col;
#pragma unroll
  for (int kk = 0; kk < 8; kk++) {
    int n = tid + (kk << 8);
    float2 v = make_float2(0.f, 0.f);
    if (n < NPIX) v = cmul(g_B[base + (size_t)n*NPIX], g_Achirp[n]);
    s[n] = v;
  }
  conv_core(s, tid);
#pragma unroll
  for (int kk = 0; kk < 3; kk++) {
    int n = tid + (kk << 8);
    if (n < NPIX) {
      float2 S = cmul(s[n], g_Achirp[n]);
      spec[n] = cmul(S, g_Kotf[((size_t)b*NPIX + n)*NPIX + col]);
    }
  }
  __syncthreads();
#pragma unroll
  for (int kk = 0; kk < 8; kk++) {
    int n = tid + (kk << 8);
    float2 v = make_float2(0.f, 0.f);
    if (n < NPIX) { float2 z = spec[n]; z.y = -z.y; v = cmul(z, g_Achirp[n]); }
    s[n] = v;
  }
  conv_core(s, tid);
#pragma unroll
  for (int kk = 0; kk < 3; kk++) {
    int n = tid + (kk << 8);
    if (n < NPIX) {
      float2 r = cmul(s[n], g_Achirp[n]);
      g_B[base + (size_t)n*NPIX] = make_float2(r.x*INV542, -r.y*INV542);
    }
  }
}

// inverse row DFT of B (blurred) + alpha blend into A
__global__ void row_inv_update() {
  __shared__ float2 s[M2048];
  int row = blockIdx.x, im = blockIdx.y, tid = threadIdx.x, b = im >> 1;
  size_t base = ((size_t)im*NPIX + row) * NPIX;
#pragma unroll
  for (int kk = 0; kk < 8; kk++) {
    int n = tid + (kk << 8);
    float2 v = make_float2(0.f, 0.f);
    if (n < NPIX) { float2 z = g_B[base + n]; z.y = -z.y; v = cmul(z, g_Achirp[n]); }
    s[n] = v;
  }
  conv_core(s, tid);
  float v0 = g_v[(b*2+0)*NPIX + row];
#pragma unroll
  for (int kk = 0; kk < 3; kk++) {
    int n = tid + (kk << 8);
    if (n < NPIX) {
      float2 r = cmul(s[n], g_Achirp[n]);
      float2 blur = make_float2(r.x*INV542, -r.y*INV542);
      float a = v0 * g_v[(b*2+1)*NPIX + n];
      float2 x = g_A[base + n];
      g_A[base + n] = make_float2(a*x.x + (1.f-a)*blur.x, a*x.y + (1.f-a)*blur.y);
    }
  }
}

// generic column pass for the final stage: which=0 -> B, which=1 -> A; inv flag
__global__ void colfft_dir(int which, int invdir) {
  __shared__ float2 s[M2048];
  int col = blockIdx.x, im = blockIdx.y, tid = threadIdx.x;
  float2* buf = which ? g_A : g_B;
  size_t base = (size_t)im*NPIX2 + col;
#pragma unroll
  for (int kk = 0; kk < 8; kk++) {
    int n = tid + (kk << 8);
    float2 v = make_float2(0.f, 0.f);
    if (n < NPIX) {
      float2 z = buf[base + (size_t)n*NPIX];
      if (invdir) z.y = -z.y;
      v = cmul(z, g_Achirp[n]);
    }
    s[n] = v;
  }
  conv_core(s, tid);
#pragma unroll
  for (int kk = 0; kk < 3; kk++) {
    int n = tid + (kk << 8);
    if (n < NPIX) {
      float2 r = cmul(s[n], g_Achirp[n]);
      if (invdir) { r.x *= INV542; r.y = -r.y * INV542; }
      buf[base + (size_t)n*NPIX] = r;
    }
  }
}

// Wiener filter in spectrum: read full spectrum from B, write filtered to A.
// p==0 images: Hermitian unpack (c0,c1), per-channel Omega, repack.
__global__ void wiener_filter(const float* __restrict__ lam) {
  int u = blockIdx.x, im = blockIdx.y, tid = threadIdx.x;
  int b = im >> 1, p = im & 1;
  float el = expf(lam[0]);
  int mu = (NPIX - u) % NPIX;
  for (int v = tid; v < NPIX; v += blockDim.x) {
    float2 Dk = g_Kotf[((size_t)b*NPIX + u)*NPIX + v];
    float dk2 = Dk.x*Dk.x + Dk.y*Dk.y;
    float2 Dkc = make_float2(Dk.x, -Dk.y);
    size_t idx = (size_t)im*NPIX2 + (size_t)u*NPIX + v;
    float2 Z = g_B[idx];
    float2 Y;
    if (p == 0) {
      int mv = (NPIX - v) % NPIX;
      float2 Zm = g_B[(size_t)im*NPIX2 + (size_t)mu*NPIX + mv];
      float2 F0 = make_float2(0.5f*(Z.x + Zm.x),  0.5f*(Z.y - Zm.y));
      float2 F1 = make_float2(0.5f*(Z.y + Zm.y), -0.5f*(Z.x - Zm.x));
      float om0 = 1.f / (dk2 + el * g_Gsum[(size_t)(0*NPIX + u)*NPIX + v]);
      float om1 = 1.f / (dk2 + el * g_Gsum[(size_t)(1*NPIX + u)*NPIX + v]);
      float2 Y0 = cmul(F0, Dkc); Y0.x *= om0; Y0.y *= om0;
      float2 Y1 = cmul(F1, Dkc); Y1.x *= om1; Y1.y *= om1;
      Y = make_float2(Y0.x - Y1.y, Y0.y + Y1.x);
    } else {
      float om2 = 1.f / (dk2 + el * g_Gsum[(size_t)(2*NPIX + u)*NPIX + v]);
      Y = cmul(Z, Dkc); Y.x *= om2; Y.y *= om2;
    }
    g_A[idx] = Y;
  }
}

// final inverse row DFT of A + unpack channels to output
__global__ void row_inv_out(float* __restrict__ out) {
  __shared__ float2 s[M2048];
  int row = blockIdx.x, im = blockIdx.y, tid = threadIdx.x;
  int b = im >> 1, p = im & 1;
  size_t base = ((size_t)im*NPIX + row) * NPIX;
#pragma unroll
  for (int kk = 0; kk < 8; kk++) {
    int n = tid + (kk << 8);
    float2 v = make_float2(0.f, 0.f);
    if (n < NPIX) { float2 z = g_A[base + n]; z.y = -z.y; v = cmul(z, g_Achirp[n]); }
    s[n] = v;
  }
  conv_core(s, tid);
#pragma unroll
  for (int kk = 0; kk < 3; kk++) {
    int n = tid + (kk << 8);
    if (n < NPIX) {
      float2 r = cmul(s[n], g_Achirp[n]);
      float re =  r.x * INV542;
      float imv = -r.y * INV542;
      if (p == 0) {
        out[(((size_t)b*3 + 0)*NPIX + row)*NPIX + n] = re;
        out[(((size_t)b*3 + 1)*NPIX + row)*NPIX + n] = imv;
      } else {
        out[(((size_t)b*3 + 2)*NPIX + row)*NPIX + n] = re;
      }
    }
  }
}

// ---------------- launch ------------------------------------------------------
extern "C" void kernel_launch(void* const* d_in, const int* in_sizes, int n_in,
                              void* d_out, int out_size) {
  const float* y    = (const float*)d_in[0];
  const float* k    = (const float*)d_in[1];
  const float* lam  = (const float*)d_in[2];
  const float* filt = (const float*)d_in[3];
  float* out = (float*)d_out;

  init_tables<<<4, 256>>>();
  init_bhat<<<1, 256>>>();
  compute_v<<<NBATCH, 32>>>(k);
  kotf_pass1<<<dim3(NPIX, NBATCH), 32>>>(k);
  kotf_pass2<<<dim3(NPIX, NBATCH), 256>>>();
  gsum_kernel<<<dim3(NPIX, 3), 256>>>(filt);
  pad_pack<<<8192, 256>>>(y);

  dim3 fgrid(NPIX, NIMG);
  for (int t = 0; t < 3; t++) {
    rowfft_fwd<<<fgrid, 256>>>();
    colfft_otf<<<fgrid, 256>>>();
    row_inv_update<<<fgrid, 256>>>();
  }
  // final Wiener stage
  rowfft_fwd<<<fgrid, 256>>>();
  colfft_dir<<<fgrid, 256>>>(0, 0);   // forward cols on B -> full spectrum
  wiener_filter<<<fgrid, 256>>>(lam); // B -> A (filtered spectrum)
  colfft_dir<<<fgrid, 256>>>(1, 1);   // inverse cols on A
  row_inv_out<<<fgrid, 256>>>(out);   // inverse rows + unpack to output
}

// round 3
// speedup vs baseline: 2.2044x; 2.2044x over previous
#include <cuda_runtime.h>
#include <math.h>

#define NPIX   542
#define NPIX2  (NPIX*NPIX)
#define NIMG   16
#define M2048  2048
#define KH     31
#define NF     8
#define NBATCH 8
#define INV542 (1.0f/542.0f)
#define PADI(i) ((i) + ((i) >> 4))
#define SPAD   2176

// ---------------- scratch (static device globals; no allocation) -------------
__device__ float2 g_A[NIMG*NPIX2];        // working images (packed complex)
__device__ float2 g_B[NIMG*NPIX2];        // spectra / blurred
__device__ float2 g_Kotf[NBATCH*NPIX2];   // per-batch blur OTF
__device__ float  g_Gsum[3*NPIX2];        // sum_f |Dg|^2 per channel
__device__ float2 g_T[NBATCH*NPIX*KH];    // OTF intermediate
__device__ float  g_v[NBATCH*2*NPIX];     // edgetaper 1D windows
__device__ float2 g_W[M2048];             // W_2048^{-t}
__device__ float2 g_Achirp[NPIX];         // Bluestein chirp a[n]=e^{-i pi n^2/542}
__device__ float2 g_E542[NPIX];           // e^{-2 pi i t/542}
__device__ __align__(16) float2 g_Bhat[M2048];  // DIF-scrambled FFT(chirp b)/2048

__device__ __forceinline__ float2 cmul(float2 a, float2 b) {
  return make_float2(a.x*b.x - a.y*b.y, a.x*b.y + a.y*b.x);
}
__device__ __forceinline__ float2 cadd(float2 a, float2 b){return make_float2(a.x+b.x,a.y+b.y);}
__device__ __forceinline__ float2 csub(float2 a, float2 b){return make_float2(a.x-b.x,a.y-b.y);}
__device__ __forceinline__ float2 mineg(float2 a){return make_float2(a.y,-a.x);}  // -i*a
__device__ __forceinline__ float2 mipos(float2 a){return make_float2(-a.y,a.x);}  // +i*a

#define SQ8 0.70710678118654752f

// radix-8 butterflies: v_k = sum_j u_j e^{-+2 pi i jk/8}
__device__ __forceinline__ void bfly8_fwd(float2* u){
  float2 t0=cadd(u[0],u[4]), t4=csub(u[0],u[4]);
  float2 t1=cadd(u[1],u[5]), t5=csub(u[1],u[5]);
  float2 t2=cadd(u[2],u[6]), t6=mineg(csub(u[2],u[6]));
  float2 t3=cadd(u[3],u[7]), t7=mineg(csub(u[3],u[7]));
  float2 a0=cadd(t0,t2), a1=csub(t0,t2);
  float2 c0=cadd(t1,t3), c1=csub(t1,t3);
  float2 b0=cadd(t4,t6), b1=csub(t4,t6);
  float2 d0=cadd(t5,t7), d1=csub(t5,t7);
  float2 w1d = make_float2(SQ8*(d0.x+d0.y), SQ8*(d0.y-d0.x));   // (SQ,-SQ)*d0
  float2 w3d = make_float2(SQ8*(d1.y-d1.x), -SQ8*(d1.x+d1.y));  // (-SQ,-SQ)*d1
  float2 mc1 = mineg(c1);
  u[0]=cadd(a0,c0); u[4]=csub(a0,c0);
  u[2]=cadd(a1,mc1); u[6]=csub(a1,mc1);
  u[1]=cadd(b0,w1d); u[5]=csub(b0,w1d);
  u[3]=cadd(b1,w3d); u[7]=csub(b1,w3d);
}
__device__ __forceinline__ void bfly8_inv(float2* u){
  float2 t0=cadd(u[0],u[4]), t4=csub(u[0],u[4]);
  float2 t1=cadd(u[1],u[5]), t5=csub(u[1],u[5]);
  float2 t2=cadd(u[2],u[6]), t6=mipos(csub(u[2],u[6]));
  float2 t3=cadd(u[3],u[7]), t7=mipos(csub(u[3],u[7]));
  float2 a0=cadd(t0,t2), a1=csub(t0,t2);
  float2 c0=cadd(t1,t3), c1=csub(t1,t3);
  float2 b0=cadd(t4,t6), b1=csub(t4,t6);
  float2 d0=cadd(t5,t7), d1=csub(t5,t7);
  float2 w1d = make_float2(SQ8*(d0.x-d0.y), SQ8*(d0.x+d0.y));   // (SQ, SQ)*d0
  float2 w3d = make_float2(-SQ8*(d1.x+d1.y), SQ8*(d1.x-d1.y));  // (-SQ, SQ)*d1
  float2 pc1 = mipos(c1);
  u[0]=cadd(a0,c0); u[4]=csub(a0,c0);
  u[2]=cadd(a1,pc1); u[6]=csub(a1,pc1);
  u[1]=cadd(b0,w1d); u[5]=csub(b0,w1d);
  u[3]=cadd(b1,w3d); u[7]=csub(b1,w3d);
}

// DIF forward radix-8 stage: distance D, twiddle exponent = (i*k) << SH
template<int D, int SH>
__device__ __forceinline__ void fwd8s(float2* s, int tid) {
  int i = tid & (D-1);
  int base = ((tid - i) << 3) + i;
  float2 u[8];
#pragma unroll
  for (int j = 0; j < 8; j++) u[j] = s[PADI(base + j*D)];
  bfly8_fwd(u);
#pragma unroll
  for (int k = 1; k < 8; k++) u[k] = cmul(u[k], g_W[(i*k) << SH]);
#pragma unroll
  for (int k = 0; k < 8; k++) s[PADI(base + k*D)] = u[k];
}

// DIT inverse radix-8 stage: twiddle (conjugated) BEFORE butterfly
template<int D, int SH>
__device__ __forceinline__ void inv8s(float2* s, int tid) {
  int i = tid & (D-1);
  int base = ((tid - i) << 3) + i;
  float2 u[8];
#pragma unroll
  for (int j = 0; j < 8; j++) u[j] = s[PADI(base + j*D)];
#pragma unroll
  for (int j = 1; j < 8; j++) {
    float2 w = g_W[(i*j) << SH];
    u[j] = cmul(u[j], make_float2(w.x, -w.y));
  }
  bfly8_inv(u);
#pragma unroll
  for (int k = 0; k < 8; k++) s[PADI(base + k*D)] = u[k];
}

// fused: final fwd radix-4 stage + pointwise Bhat + first inv radix-4 stage
__device__ __forceinline__ void mid4(float2* s, int tid) {
#pragma unroll
  for (int h = 0; h < 2; h++) {
    int g = tid + (h << 8);
    float2 u0=s[PADI(4*g)], u1=s[PADI(4*g+1)], u2=s[PADI(4*g+2)], u3=s[PADI(4*g+3)];
    float2 e0=cadd(u0,u2), e1=csub(u0,u2);
    float2 o0=cadd(u1,u3), o1=mineg(csub(u1,u3));
    float2 v0=cadd(e0,o0), v2=csub(e0,o0), v1=cadd(e1,o1), v3=csub(e1,o1);
    const float4* bp = (const float4*)(g_Bhat + 4*g);
    float4 ba = bp[0], bb = bp[1];
    v0 = cmul(v0, make_float2(ba.x,ba.y)); v1 = cmul(v1, make_float2(ba.z,ba.w));
    v2 = cmul(v2, make_float2(bb.x,bb.y)); v3 = cmul(v3, make_float2(bb.z,bb.w));
    float2 f0=cadd(v0,v2), f1=csub(v0,v2);
    float2 p0=cadd(v1,v3), p1=mipos(csub(v1,v3));
    s[PADI(4*g)]  =cadd(f0,p0); s[PADI(4*g+2)]=csub(f0,p0);
    s[PADI(4*g+1)]=cadd(f1,p1); s[PADI(4*g+3)]=csub(f1,p1);
  }
}

// circular convolution with chirp b: s (chirped, zero-padded input) -> conv result
__device__ __forceinline__ void conv_core8(float2* s, int tid) {
  // forward DIF (no reorder needed: pointwise multiply done in scrambled order)
  fwd8s<256,0>(s, tid); __syncthreads();
  fwd8s<32,3>(s, tid);  __syncthreads();
  fwd8s<4,6>(s, tid);   __syncthreads();
  mid4(s, tid);         __syncthreads();
  inv8s<4,6>(s, tid);   __syncthreads();
  inv8s<32,3>(s, tid);  __syncthreads();
  inv8s<256,0>(s, tid); __syncthreads();
}

// forward-only DIF (for building scrambled Bhat)
__device__ __forceinline__ void fwd_only(float2* s, int tid) {
  fwd8s<256,0>(s, tid); __syncthreads();
  fwd8s<32,3>(s, tid);  __syncthreads();
  fwd8s<4,6>(s, tid);   __syncthreads();
#pragma unroll
  for (int h = 0; h < 2; h++) {
    int g = tid + (h << 8);
    float2 u0=s[PADI(4*g)], u1=s[PADI(4*g+1)], u2=s[PADI(4*g+2)], u3=s[PADI(4*g+3)];
    float2 e0=cadd(u0,u2), e1=csub(u0,u2);
    float2 o0=cadd(u1,u3), o1=mineg(csub(u1,u3));
    s[PADI(4*g)]  =cadd(e0,o0); s[PADI(4*g+2)]=csub(e0,o0);
    s[PADI(4*g+1)]=cadd(e1,o1); s[PADI(4*g+3)]=csub(e1,o1);
  }
  __syncthreads();
}

// ---------------- table init -------------------------------------------------
__global__ void init_tables() {
  int t = blockIdx.x * blockDim.x + threadIdx.x;
  if (t < M2048) {
    double a = -(2.0 * M_PI / (double)M2048) * (double)t;
    g_W[t] = make_float2((float)cos(a), (float)sin(a));
  }
  if (t < NPIX) {
    long long m = ((long long)t * t) % (2*NPIX);
    double a = -(M_PI / (double)NPIX) * (double)m;
    g_Achirp[t] = make_float2((float)cos(a), (float)sin(a));
    double a2 = -(2.0 * M_PI / (double)NPIX) * (double)t;
    g_E542[t] = make_float2((float)cos(a2), (float)sin(a2));
  }
}

__global__ void __launch_bounds__(256) init_bhat() {
  __shared__ float2 s[SPAD];
  int tid = threadIdx.x;
#pragma unroll
  for (int kk = 0; kk < 8; kk++) {
    int n = tid + (kk << 8);
    float2 v = make_float2(0.f, 0.f);
    if (n < NPIX)            { float2 a = g_Achirp[n];         v = make_float2(a.x, -a.y); }
    else if (n > M2048-NPIX) { float2 a = g_Achirp[M2048 - n]; v = make_float2(a.x, -a.y); }
    s[PADI(n)] = v;
  }
  __syncthreads();
  fwd_only(s, tid);
#pragma unroll
  for (int kk = 0; kk < 8; kk++) {
    int n = tid + (kk << 8);
    float2 z = s[PADI(n)];
    g_Bhat[n] = make_float2(z.x * (1.f/M2048), z.y * (1.f/M2048));
  }
}

// ---------------- edgetaper alpha windows (direct autocorrelation) ------------
__global__ void compute_v(const float* __restrict__ k) {
  int b = blockIdx.x, tid = threadIdx.x;           // 32 threads
  __shared__ float p0[KH], p1[KH], r0a[KH], r1a[KH];
  if (tid < KH) {
    float s0 = 0.f, s1 = 0.f;
    for (int j = 0; j < KH; j++) {
      s0 += k[b*KH*KH + tid*KH + j];
      s1 += k[b*KH*KH + j*KH + tid];
    }
    p0[tid] = s0; p1[tid] = s1;
  }
  __syncthreads();
  if (tid < KH) {
    float a0 = 0.f, a1 = 0.f;
    for (int m = 0; m + tid < KH; m++) { a0 += p0[m]*p0[m+tid]; a1 += p1[m]*p1[m+tid]; }
    r0a[tid] = a0; r1a[tid] = a1;
  }
  __syncthreads();
  float inv0 = 1.f / r0a[0], inv1 = 1.f / r1a[0];
  for (int n = tid; n < NPIX; n += 32) {
    float z0 = 0.f, z1 = 0.f;
    if (n <= KH-1)                         { z0 = r0a[n];            z1 = r1a[n]; }
    else if (n >= NPIX-KH && n <= NPIX-2)  { z0 = r0a[(NPIX-1) - n]; z1 = r1a[(NPIX-1) - n]; }
    else if (n == NPIX-1)                  { z0 = r0a[0];            z1 = r1a[0]; }
    g_v[(b*2+0)*NPIX + n] = 1.f - z0 * inv0;
    g_v[(b*2+1)*NPIX + n] = 1.f - z1 * inv1;
  }
}

// ---------------- direct-DFT OTFs --------------------------------------------
__global__ void kotf_pass1(const float* __restrict__ k) {
  int u = blockIdx.x, b = blockIdx.y, j = threadIdx.x;
  if (j >= KH) return;
  float2 acc = make_float2(0.f, 0.f);
  for (int i = 0; i < KH; i++) {
    int m = u * (i - 15);
    int idx = m % NPIX; if (idx < 0) idx += NPIX;
    float2 e = g_E542[idx];
    float  w = k[b*KH*KH + i*KH + j];
    acc.x += w*e.x; acc.y += w*e.y;
  }
  g_T[(b*NPIX + u)*KH + j] = acc;
}

__global__ void kotf_pass2() {
  int u = blockIdx.x, b = blockIdx.y, tid = threadIdx.x;
  __shared__ float2 Ts[KH];
  if (tid < KH) Ts[tid] = g_T[(b*NPIX + u)*KH + tid];
  __syncthreads();
  for (int v = tid; v < NPIX; v += blockDim.x) {
    float2 acc = make_float2(0.f, 0.f);
    for (int j = 0; j < KH; j++) {
      int m = v * (j - 15);
      int idx = m % NPIX; if (idx < 0) idx += NPIX;
      float2 e = g_E542[idx], t = Ts[j];
      acc.x += t.x*e.x - t.y*e.y;
      acc.y += t.x*e.y + t.y*e.x;
    }
    g_Kotf[(b*NPIX + u)*NPIX + v] = acc;
  }
}

__global__ void gsum_kernel(const float* __restrict__ filt) {
  int u = blockIdx.x, c = blockIdx.y, tid = threadIdx.x;
  __shared__ float f[NF*9];
  if (tid < NF*9) { int ff = tid/9, t = tid%9; f[tid] = filt[(ff*3 + c)*9 + t]; }
  __syncthreads();
  for (int v = tid; v < NPIX; v += blockDim.x) {
    float sum = 0.f;
    for (int ff = 0; ff < NF; ff++) {
      float ar = 0.f, ai = 0.f;
#pragma unroll
      for (int t = 0; t < 9; t++) {
        int i = t/3, j = t%3;
        int sgn = u*(i-1) + v*(j-1);
        int idx = sgn % NPIX; if (idx < 0) idx += NPIX;
        float2 e = g_E542[idx]; float w = f[ff*9 + t];
        ar += w*e.x; ai += w*e.y;
      }
      sum += ar*ar + ai*ai;
    }
    g_Gsum[(c*NPIX + u)*NPIX + v] = sum;
  }
}

// ---------------- pad (edge replicate) + channel pack ------------------------
__global__ void pad_pack(const float* __restrict__ y) {
  int total = NIMG*NPIX2;
  for (int n = blockIdx.x*blockDim.x + threadIdx.x; n < total; n += gridDim.x*blockDim.x) {
    int im = n / NPIX2, rem = n % NPIX2;
    int i = rem / NPIX, j = rem % NPIX;
    int b = im >> 1, p = im & 1;
    int yi = min(max(i - 15, 0), 511), yj = min(max(j - 15, 0), 511);
    const float* yb = y + (size_t)b * 3 * 262144;
    float2 v;
    if (p == 0) v = make_float2(yb[yi*512 + yj], yb[262144 + yi*512 + yj]);
    else        v = make_float2(yb[2*262144 + yi*512 + yj], 0.f);
    g_A[n] = v;
  }
}

// ---------------- FFT pass kernels -------------------------------------------
__global__ void __launch_bounds__(256) rowfft_fwd() {   // A -> B, forward DFT along rows
  __shared__ float2 s[SPAD];
  int row = blockIdx.x, im = blockIdx.y, tid = threadIdx.x;
  size_t base = ((size_t)im*NPIX + row) * NPIX;
#pragma unroll
  for (int kk = 0; kk < 8; kk++) {
    int n = tid + (kk << 8);
    float2 v = make_float2(0.f, 0.f);
    if (n < NPIX) v = cmul(g_A[base + n], g_Achirp[n]);
    s[PADI(n)] = v;
  }
  conv_core8(s, tid);
#pragma unroll
  for (int kk = 0; kk < 3; kk++) {
    int n = tid + (kk << 8);
    if (n < NPIX) g_B[base + n] = cmul(s[PADI(n)], g_Achirp[n]);
  }
}

// fused: forward col DFT + OTF multiply + inverse col DFT, in-place on B
__global__ void __launch_bounds__(256) colfft_otf() {
  __shared__ float2 s[SPAD];
  int col = blockIdx.x, im = blockIdx.y, tid = threadIdx.x, b = im >> 1;
  size_t base = (size_t)im*NPIX2 + col;
#pragma unroll
  for (int kk = 0; kk < 8; kk++) {
    int n = tid + (kk << 8);
    float2 v = make_float2(0.f, 0.f);
    if (n < NPIX) v = cmul(g_B[base + (size_t)n*NPIX], g_Achirp[n]);
    s[PADI(n)] = v;
  }
  conv_core8(s, tid);
  float2 sp[3];
#pragma unroll
  for (int kk = 0; kk < 3; kk++) {
    int n = tid + (kk << 8);
    if (n < NPIX) {
      float2 S = cmul(s[PADI(n)], g_Achirp[n]);
      sp[kk] = cmul(S, g_Kotf[((size_t)b*NPIX + n)*NPIX + col]);
    }
  }
#pragma unroll
  for (int kk = 0; kk < 8; kk++) {
    int n = tid + (kk << 8);
    float2 v = make_float2(0.f, 0.f);
    if (kk < 3 && n < NPIX) { float2 z = sp[kk]; z.y = -z.y; v = cmul(z, g_Achirp[n]); }
    s[PADI(n)] = v;
  }
  conv_core8(s, tid);
#pragma unroll
  for (int kk = 0; kk < 3; kk++) {
    int n = tid + (kk << 8);
    if (n < NPIX) {
      float2 r = cmul(s[PADI(n)], g_Achirp[n]);
      g_B[base + (size_t)n*NPIX] = make_float2(r.x*INV542, -r.y*INV542);
    }
  }
}

// fused per-iteration row pass: inverse row DFT of B (blurred) + alpha blend
// into A + forward row DFT of the new image back into B.
__global__ void __launch_bounds__(256) row_iter() {
  __shared__ float2 s[SPAD];
  int row = blockIdx.x, im = blockIdx.y, tid = threadIdx.x, b = im >> 1;
  size_t base = ((size_t)im*NPIX + row) * NPIX;
#pragma unroll
  for (int kk = 0; kk < 8; kk++) {
    int n = tid + (kk << 8);
    float2 v = make_float2(0.f, 0.f);
    if (n < NPIX) { float2 z = g_B[base + n]; z.y = -z.y; v = cmul(z, g_Achirp[n]); }
    s[PADI(n)] = v;
  }
  conv_core8(s, tid);
  float v0 = g_v[(b*2+0)*NPIX + row];
  float2 nv[3];
#pragma unroll
  for (int kk = 0; kk < 3; kk++) {
    int n = tid + (kk << 8);
    nv[kk] = make_float2(0.f, 0.f);
    if (n < NPIX) {
      float2 r = cmul(s[PADI(n)], g_Achirp[n]);
      float2 blur = make_float2(r.x*INV542, -r.y*INV542);
      float a = v0 * g_v[(b*2+1)*NPIX + n];
      float2 x = g_A[base + n];
      float2 t = make_float2(a*x.x + (1.f-a)*blur.x, a*x.y + (1.f-a)*blur.y);
      nv[kk] = t;
      g_A[base + n] = t;
    }
  }
  // forward DFT of the blended row (slot-ownership: no sync needed before refill)
#pragma unroll
  for (int kk = 0; kk < 8; kk++) {
    int n = tid + (kk << 8);
    float2 v = make_float2(0.f, 0.f);
    if (kk < 3 && n < NPIX) v = cmul(nv[kk], g_Achirp[n]);
    s[PADI(n)] = v;
  }
  conv_core8(s, tid);
#pragma unroll
  for (int kk = 0; kk < 3; kk++) {
    int n = tid + (kk << 8);
    if (n < NPIX) g_B[base + n] = cmul(s[PADI(n)], g_Achirp[n]);
  }
}

// generic column pass for the final stage: which=0 -> B, which=1 -> A; inv flag
__global__ void __launch_bounds__(256) colfft_dir(int which, int invdir) {
  __shared__ float2 s[SPAD];
  int col = blockIdx.x, im = blockIdx.y, tid = threadIdx.x;
  float2* buf = which ? g_A : g_B;
  size_t base = (size_t)im*NPIX2 + col;
#pragma unroll
  for (int kk = 0; kk < 8; kk++) {
    int n = tid + (kk << 8);
    float2 v = make_float2(0.f, 0.f);
    if (n < NPIX) {
      float2 z = buf[base + (size_t)n*NPIX];
      if (invdir) z.y = -z.y;
      v = cmul(z, g_Achirp[n]);
    }
    s[PADI(n)] = v;
  }
  conv_core8(s, tid);
#pragma unroll
  for (int kk = 0; kk < 3; kk++) {
    int n = tid + (kk << 8);
    if (n < NPIX) {
      float2 r = cmul(s[PADI(n)], g_Achirp[n]);
      if (invdir) { r.x *= INV542; r.y = -r.y * INV542; }
      buf[base + (size_t)n*NPIX] = r;
    }
  }
}

// Wiener filter in spectrum: read full spectrum from B, write filtered to A.
__global__ void wiener_filter(const float* __restrict__ lam) {
  int u = blockIdx.x, im = blockIdx.y, tid = threadIdx.x;
  int b = im >> 1, p = im & 1;
  float el = expf(lam[0]);
  int mu = (NPIX - u) % NPIX;
  for (int v = tid; v < NPIX; v += blockDim.x) {
    float2 Dk = g_Kotf[((size_t)b*NPIX + u)*NPIX + v];
    float dk2 = Dk.x*Dk.x + Dk.y*Dk.y;
    float2 Dkc = make_float2(Dk.x, -Dk.y);
    size_t idx = (size_t)im*NPIX2 + (size_t)u*NPIX + v;
    float2 Z = g_B[idx];
    float2 Y;
    if (p == 0) {
      int mv = (NPIX - v) % NPIX;
      float2 Zm = g_B[(size_t)im*NPIX2 + (size_t)mu*NPIX + mv];
      float2 F0 = make_float2(0.5f*(Z.x + Zm.x),  0.5f*(Z.y - Zm.y));
      float2 F1 = make_float2(0.5f*(Z.y + Zm.y), -0.5f*(Z.x - Zm.x));
      float om0 = 1.f / (dk2 + el * g_Gsum[(size_t)(0*NPIX + u)*NPIX + v]);
      float om1 = 1.f / (dk2 + el * g_Gsum[(size_t)(1*NPIX + u)*NPIX + v]);
      float2 Y0 = cmul(F0, Dkc); Y0.x *= om0; Y0.y *= om0;
      float2 Y1 = cmul(F1, Dkc); Y1.x *= om1; Y1.y *= om1;
      Y = make_float2(Y0.x - Y1.y, Y0.y + Y1.x);
    } else {
      float om2 = 1.f / (dk2 + el * g_Gsum[(size_t)(2*NPIX + u)*NPIX + v]);
      Y = cmul(Z, Dkc); Y.x *= om2; Y.y *= om2;
    }
    g_A[idx] = Y;
  }
}

// final inverse row DFT of A + unpack channels to output
__global__ void __launch_bounds__(256) row_inv_out(float* __restrict__ out) {
  __shared__ float2 s[SPAD];
  int row = blockIdx.x, im = blockIdx.y, tid = threadIdx.x;
  int b = im >> 1, p = im & 1;
  size_t base = ((size_t)im*NPIX + row) * NPIX;
#pragma unroll
  for (int kk = 0; kk < 8; kk++) {
    int n = tid + (kk << 8);
    float2 v = make_float2(0.f, 0.f);
    if (n < NPIX) { float2 z = g_A[base + n]; z.y = -z.y; v = cmul(z, g_Achirp[n]); }
    s[PADI(n)] = v;
  }
  conv_core8(s, tid);
#pragma unroll
  for (int kk = 0; kk < 3; kk++) {
    int n = tid + (kk << 8);
    if (n < NPIX) {
      float2 r = cmul(s[PADI(n)], g_Achirp[n]);
      float re  =  r.x * INV542;
      float imv = -r.y * INV542;
      if (p == 0) {
        out[(((size_t)b*3 + 0)*NPIX + row)*NPIX + n] = re;
        out[(((size_t)b*3 + 1)*NPIX + row)*NPIX + n] = imv;
      } else {
        out[(((size_t)b*3 + 2)*NPIX + row)*NPIX + n] = re;
      }
    }
  }
}

// ---------------- launch ------------------------------------------------------
extern "C" void kernel_launch(void* const* d_in, const int* in_sizes, int n_in,
                              void* d_out, int out_size) {
  const float* y    = (const float*)d_in[0];
  const float* k    = (const float*)d_in[1];
  const float* lam  = (const float*)d_in[2];
  const float* filt = (const float*)d_in[3];
  float* out = (float*)d_out;

  init_tables<<<8, 256>>>();
  init_bhat<<<1, 256>>>();
  compute_v<<<NBATCH, 32>>>(k);
  kotf_pass1<<<dim3(NPIX, NBATCH), 32>>>(k);
  kotf_pass2<<<dim3(NPIX, NBATCH), 256>>>();
  gsum_kernel<<<dim3(NPIX, 3), 256>>>(filt);
  pad_pack<<<8192, 256>>>(y);

  dim3 fgrid(NPIX, NIMG);
  rowfft_fwd<<<fgrid, 256>>>();
  for (int t = 0; t < 3; t++) {
    colfft_otf<<<fgrid, 256>>>();
    row_iter<<<fgrid, 256>>>();
  }
  // final Wiener stage
  colfft_dir<<<fgrid, 256>>>(0, 0);   // forward cols on B -> full spectrum
  wiener_filter<<<fgrid, 256>>>(lam); // B -> A (filtered spectrum)
  colfft_dir<<<fgrid, 256>>>(1, 1);   // inverse cols on A
  row_inv_out<<<fgrid, 256>>>(out);   // inverse rows + unpack to output
}

// round 4
// speedup vs baseline: 3.0565x; 1.3865x over previous
#include <cuda_runtime.h>
#include <math.h>

#define NPIX   542
#define NPIX2  (NPIX*NPIX)
#define NIMG   16
#define M2048  2048
#define KH     31
#define NF     8
#define NBATCH 8
#define INV542 (1.0f/542.0f)
#define PADI(i) ((i) + ((i) >> 4))
#define SPAD   2176

// ---------------- scratch (static device globals; no allocation) -------------
__device__ float2 g_A[NIMG*NPIX2];
__device__ float2 g_B[NIMG*NPIX2];
__device__ float2 g_Kotf[NBATCH*NPIX2];
__device__ float  g_Gsum[3*NPIX2];
__device__ float2 g_T[NBATCH*NPIX*KH];
__device__ float  g_v[NBATCH*2*NPIX];
__device__ float2 g_W[M2048];             // W_2048^{-t}
__device__ float2 g_Achirp[NPIX];
__device__ float2 g_E542[NPIX];
__device__ __align__(16) float2 g_Bhat[M2048];  // scrambled FFT(chirp b)/2048

__device__ __forceinline__ float2 cmul(float2 a, float2 b) {
  return make_float2(a.x*b.x - a.y*b.y, a.x*b.y + a.y*b.x);
}
__device__ __forceinline__ float2 cadd(float2 a, float2 b){return make_float2(a.x+b.x,a.y+b.y);}
__device__ __forceinline__ float2 csub(float2 a, float2 b){return make_float2(a.x-b.x,a.y-b.y);}
__device__ __forceinline__ float2 mineg(float2 a){return make_float2(a.y,-a.x);}  // -i*a
__device__ __forceinline__ float2 mipos(float2 a){return make_float2(-a.y,a.x);}  // +i*a

#define SQ8 0.70710678118654752f
#define C16 0.92387953251128675613f
#define S16 0.38268343236508977173f

// ---------------- radix-8 butterflies (natural order in/out) ------------------
__device__ __forceinline__ void bfly8_fwd(float2* u){
  float2 t0=cadd(u[0],u[4]), t4=csub(u[0],u[4]);
  float2 t1=cadd(u[1],u[5]), t5=csub(u[1],u[5]);
  float2 t2=cadd(u[2],u[6]), t6=mineg(csub(u[2],u[6]));
  float2 t3=cadd(u[3],u[7]), t7=mineg(csub(u[3],u[7]));
  float2 a0=cadd(t0,t2), a1=csub(t0,t2);
  float2 c0=cadd(t1,t3), c1=csub(t1,t3);
  float2 b0=cadd(t4,t6), b1=csub(t4,t6);
  float2 d0=cadd(t5,t7), d1=csub(t5,t7);
  float2 w1d = make_float2(SQ8*(d0.x+d0.y), SQ8*(d0.y-d0.x));
  float2 w3d = make_float2(SQ8*(d1.y-d1.x), -SQ8*(d1.x+d1.y));
  float2 mc1 = mineg(c1);
  u[0]=cadd(a0,c0); u[4]=csub(a0,c0);
  u[2]=cadd(a1,mc1); u[6]=csub(a1,mc1);
  u[1]=cadd(b0,w1d); u[5]=csub(b0,w1d);
  u[3]=cadd(b1,w3d); u[7]=csub(b1,w3d);
}
__device__ __forceinline__ void bfly8_inv(float2* u){
  float2 t0=cadd(u[0],u[4]), t4=csub(u[0],u[4]);
  float2 t1=cadd(u[1],u[5]), t5=csub(u[1],u[5]);
  float2 t2=cadd(u[2],u[6]), t6=mipos(csub(u[2],u[6]));
  float2 t3=cadd(u[3],u[7]), t7=mipos(csub(u[3],u[7]));
  float2 a0=cadd(t0,t2), a1=csub(t0,t2);
  float2 c0=cadd(t1,t3), c1=csub(t1,t3);
  float2 b0=cadd(t4,t6), b1=csub(t4,t6);
  float2 d0=cadd(t5,t7), d1=csub(t5,t7);
  float2 w1d = make_float2(SQ8*(d0.x-d0.y), SQ8*(d0.x+d0.y));
  float2 w3d = make_float2(-SQ8*(d1.x+d1.y), SQ8*(d1.x-d1.y));
  float2 pc1 = mipos(c1);
  u[0]=cadd(a0,c0); u[4]=csub(a0,c0);
  u[2]=cadd(a1,pc1); u[6]=csub(a1,pc1);
  u[1]=cadd(b0,w1d); u[5]=csub(b0,w1d);
  u[3]=cadd(b1,w3d); u[7]=csub(b1,w3d);
}

// ---------------- radix-16 butterfly (two radix-4 layers) ---------------------
__device__ __forceinline__ void dft4f(float2&a,float2&b,float2&c,float2&d){
  float2 t0=cadd(a,c), t1=csub(a,c), t2=cadd(b,d), t3=csub(b,d);
  a=cadd(t0,t2); c=csub(t0,t2); b=cadd(t1,mineg(t3)); d=cadd(t1,mipos(t3));
}
__device__ __forceinline__ void dft4i(float2&a,float2&b,float2&c,float2&d){
  float2 t0=cadd(a,c), t1=csub(a,c), t2=cadd(b,d), t3=csub(b,d);
  a=cadd(t0,t2); c=csub(t0,t2); b=cadd(t1,mipos(t3)); d=cadd(t1,mineg(t3));
}
// after bfly16_fwd, X[k] (k = k1 + 4*k0) lives in u[(k&3)*4 + (k>>2)]
__device__ __forceinline__ void bfly16_fwd(float2* u){
  dft4f(u[0],u[4],u[8],u[12]);
  dft4f(u[1],u[5],u[9],u[13]);
  dft4f(u[2],u[6],u[10],u[14]);
  dft4f(u[3],u[7],u[11],u[15]);
  u[5]  = cmul(u[5],  make_float2( C16,-S16));
  u[9]  = cmul(u[9],  make_float2( SQ8,-SQ8));
  u[13] = cmul(u[13], make_float2( S16,-C16));
  u[6]  = cmul(u[6],  make_float2( SQ8,-SQ8));
  u[10] = mineg(u[10]);
  u[14] = cmul(u[14], make_float2(-SQ8,-SQ8));
  u[7]  = cmul(u[7],  make_float2( S16,-C16));
  u[11] = cmul(u[11], make_float2(-SQ8,-SQ8));
  u[15] = cmul(u[15], make_float2(-C16, S16));
  dft4f(u[0],u[1],u[2],u[3]);
  dft4f(u[4],u[5],u[6],u[7]);
  dft4f(u[8],u[9],u[10],u[11]);
  dft4f(u[12],u[13],u[14],u[15]);
}
__device__ __forceinline__ void bfly16_inv(float2* u){
  dft4i(u[0],u[4],u[8],u[12]);
  dft4i(u[1],u[5],u[9],u[13]);
  dft4i(u[2],u[6],u[10],u[14]);
  dft4i(u[3],u[7],u[11],u[15]);
  u[5]  = cmul(u[5],  make_float2( C16, S16));
  u[9]  = cmul(u[9],  make_float2( SQ8, SQ8));
  u[13] = cmul(u[13], make_float2( S16, C16));
  u[6]  = cmul(u[6],  make_float2( SQ8, SQ8));
  u[10] = mipos(u[10]);
  u[14] = cmul(u[14], make_float2(-SQ8, SQ8));
  u[7]  = cmul(u[7],  make_float2( S16, C16));
  u[11] = cmul(u[11], make_float2(-SQ8, SQ8));
  u[15] = cmul(u[15], make_float2(-C16,-S16));
  dft4i(u[0],u[1],u[2],u[3]);
  dft4i(u[4],u[5],u[6],u[7]);
  dft4i(u[8],u[9],u[10],u[11]);
  dft4i(u[12],u[13],u[14],u[15]);
}

// DIF forward radix-16 stage: distance D, external twiddle exponent (i*k) << SH
template<int D, int SH>
__device__ __forceinline__ void fwd16s(float2* s, int tid) {
  int i = tid & (D-1);
  int base = ((tid - i) << 4) + i;
  float2 u[16];
#pragma unroll
  for (int j = 0; j < 16; j++) u[j] = s[PADI(base + j*D)];
  bfly16_fwd(u);
#pragma unroll
  for (int k = 0; k < 16; k++) {
    float2 v = u[((k & 3) << 2) | (k >> 2)];
    if (k) v = cmul(v, g_W[(i*k) << SH]);
    s[PADI(base + k*D)] = v;
  }
}
// DIT inverse radix-16 stage: conj twiddle before butterfly
template<int D, int SH>
__device__ __forceinline__ void inv16s(float2* s, int tid) {
  int i = tid & (D-1);
  int base = ((tid - i) << 4) + i;
  float2 u[16];
#pragma unroll
  for (int k = 0; k < 16; k++) {
    float2 z = s[PADI(base + k*D)];
    if (k) { float2 w = g_W[(i*k) << SH]; z = cmul(z, make_float2(w.x, -w.y)); }
    u[k] = z;
  }
  bfly16_inv(u);
#pragma unroll
  for (int k = 0; k < 16; k++) s[PADI(base + k*D)] = u[((k & 3) << 2) | (k >> 2)];
}

// fused mid: fwd radix-8 (D=1) + pointwise scrambled-Bhat + inv radix-8
__device__ __forceinline__ void mid8(float2* s, int tid) {
#pragma unroll
  for (int h = 0; h < 2; h++) {
    int g = tid + (h << 7);
    float2 u[8];
#pragma unroll
    for (int j = 0; j < 8; j++) u[j] = s[PADI(8*g + j)];
    bfly8_fwd(u);
    const float4* bp = (const float4*)(g_Bhat + 8*g);
#pragma unroll
    for (int j = 0; j < 4; j++) {
      float4 bb = bp[j];
      u[2*j]   = cmul(u[2*j],   make_float2(bb.x, bb.y));
      u[2*j+1] = cmul(u[2*j+1], make_float2(bb.z, bb.w));
    }
    bfly8_inv(u);
#pragma unroll
    for (int j = 0; j < 8; j++) s[PADI(8*g + j)] = u[j];
  }
}

// circular convolution with chirp b (5 smem round trips, 5 syncs)
__device__ __forceinline__ void conv_core16(float2* s, int tid) {
  fwd16s<128,0>(s, tid); __syncthreads();
  fwd16s<8,4>(s, tid);   __syncthreads();
  mid8(s, tid);          __syncthreads();
  inv16s<8,4>(s, tid);   __syncthreads();
  inv16s<128,0>(s, tid); __syncthreads();
}

// forward-only path (for building scrambled Bhat; must match data fwd path)
__device__ __forceinline__ void fwd_only(float2* s, int tid) {
  fwd16s<128,0>(s, tid); __syncthreads();
  fwd16s<8,4>(s, tid);   __syncthreads();
#pragma unroll
  for (int h = 0; h < 2; h++) {
    int g = tid + (h << 7);
    float2 u[8];
#pragma unroll
    for (int j = 0; j < 8; j++) u[j] = s[PADI(8*g + j)];
    bfly8_fwd(u);
#pragma unroll
    for (int j = 0; j < 8; j++) s[PADI(8*g + j)] = u[j];
  }
  __syncthreads();
}

// ---------------- table init -------------------------------------------------
__global__ void init_tables() {
  int t = blockIdx.x * blockDim.x + threadIdx.x;
  if (t < M2048) {
    double a = -(2.0 * M_PI / (double)M2048) * (double)t;
    g_W[t] = make_float2((float)cos(a), (float)sin(a));
  }
  if (t < NPIX) {
    long long m = ((long long)t * t) % (2*NPIX);
    double a = -(M_PI / (double)NPIX) * (double)m;
    g_Achirp[t] = make_float2((float)cos(a), (float)sin(a));
    double a2 = -(2.0 * M_PI / (double)NPIX) * (double)t;
    g_E542[t] = make_float2((float)cos(a2), (float)sin(a2));
  }
}

__global__ void __launch_bounds__(128) init_bhat() {
  __shared__ float2 s[SPAD];
  int tid = threadIdx.x;
#pragma unroll
  for (int kk = 0; kk < 16; kk++) {
    int n = tid + (kk << 7);
    float2 v = make_float2(0.f, 0.f);
    if (n < NPIX)            { float2 a = g_Achirp[n];         v = make_float2(a.x, -a.y); }
    else if (n > M2048-NPIX) { float2 a = g_Achirp[M2048 - n]; v = make_float2(a.x, -a.y); }
    s[PADI(n)] = v;
  }
  __syncthreads();
  fwd_only(s, tid);
#pragma unroll
  for (int kk = 0; kk < 16; kk++) {
    int n = tid + (kk << 7);
    float2 z = s[PADI(n)];
    g_Bhat[n] = make_float2(z.x * (1.f/M2048), z.y * (1.f/M2048));
  }
}

// ---------------- edgetaper alpha windows ------------------------------------
__global__ void compute_v(const float* __restrict__ k) {
  int b = blockIdx.x, tid = threadIdx.x;           // 32 threads
  __shared__ float p0[KH], p1[KH], r0a[KH], r1a[KH];
  if (tid < KH) {
    float s0 = 0.f, s1 = 0.f;
    for (int j = 0; j < KH; j++) {
      s0 += k[b*KH*KH + tid*KH + j];
      s1 += k[b*KH*KH + j*KH + tid];
    }
    p0[tid] = s0; p1[tid] = s1;
  }
  __syncthreads();
  if (tid < KH) {
    float a0 = 0.f, a1 = 0.f;
    for (int m = 0; m + tid < KH; m++) { a0 += p0[m]*p0[m+tid]; a1 += p1[m]*p1[m+tid]; }
    r0a[tid] = a0; r1a[tid] = a1;
  }
  __syncthreads();
  float inv0 = 1.f / r0a[0], inv1 = 1.f / r1a[0];
  for (int n = tid; n < NPIX; n += 32) {
    float z0 = 0.f, z1 = 0.f;
    if (n <= KH-1)                         { z0 = r0a[n];            z1 = r1a[n]; }
    else if (n >= NPIX-KH && n <= NPIX-2)  { z0 = r0a[(NPIX-1) - n]; z1 = r1a[(NPIX-1) - n]; }
    else if (n == NPIX-1)                  { z0 = r0a[0];            z1 = r1a[0]; }
    g_v[(b*2+0)*NPIX + n] = 1.f - z0 * inv0;
    g_v[(b*2+1)*NPIX + n] = 1.f - z1 * inv1;
  }
}

// ---------------- direct-DFT OTFs --------------------------------------------
__global__ void kotf_pass1(const float* __restrict__ k) {
  int u = blockIdx.x, b = blockIdx.y, j = threadIdx.x;
  if (j >= KH) return;
  float2 acc = make_float2(0.f, 0.f);
  for (int i = 0; i < KH; i++) {
    int m = u * (i - 15);
    int idx = m % NPIX; if (idx < 0) idx += NPIX;
    float2 e = g_E542[idx];
    float  w = k[b*KH*KH + i*KH + j];
    acc.x += w*e.x; acc.y += w*e.y;
  }
  g_T[(b*NPIX + u)*KH + j] = acc;
}

__global__ void kotf_pass2() {
  int u = blockIdx.x, b = blockIdx.y, tid = threadIdx.x;
  __shared__ float2 Ts[KH];
  if (tid < KH) Ts[tid] = g_T[(b*NPIX + u)*KH + tid];
  __syncthreads();
  for (int v = tid; v < NPIX; v += blockDim.x) {
    float2 acc = make_float2(0.f, 0.f);
    for (int j = 0; j < KH; j++) {
      int m = v * (j - 15);
      int idx = m % NPIX; if (idx < 0) idx += NPIX;
      float2 e = g_E542[idx], t = Ts[j];
      acc.x += t.x*e.x - t.y*e.y;
      acc.y += t.x*e.y + t.y*e.x;
    }
    g_Kotf[(b*NPIX + u)*NPIX + v] = acc;
  }
}

__global__ void gsum_kernel(const float* __restrict__ filt) {
  int u = blockIdx.x, c = blockIdx.y, tid = threadIdx.x;
  __shared__ float f[NF*9];
  if (tid < NF*9) { int ff = tid/9, t = tid%9; f[tid] = filt[(ff*3 + c)*9 + t]; }
  __syncthreads();
  for (int v = tid; v < NPIX; v += blockDim.x) {
    float sum = 0.f;
    for (int ff = 0; ff < NF; ff++) {
      float ar = 0.f, ai = 0.f;
#pragma unroll
      for (int t = 0; t < 9; t++) {
        int i = t/3, j = t%3;
        int sgn = u*(i-1) + v*(j-1);
        int idx = sgn % NPIX; if (idx < 0) idx += NPIX;
        float2 e = g_E542[idx]; float w = f[ff*9 + t];
        ar += w*e.x; ai += w*e.y;
      }
      sum += ar*ar + ai*ai;
    }
    g_Gsum[(c*NPIX + u)*NPIX + v] = sum;
  }
}

// ---------------- pad (edge replicate) + channel pack ------------------------
__global__ void pad_pack(const float* __restrict__ y) {
  int total = NIMG*NPIX2;
  for (int n = blockIdx.x*blockDim.x + threadIdx.x; n < total; n += gridDim.x*blockDim.x) {
    int im = n / NPIX2, rem = n % NPIX2;
    int i = rem / NPIX, j = rem % NPIX;
    int b = im >> 1, p = im & 1;
    int yi = min(max(i - 15, 0), 511), yj = min(max(j - 15, 0), 511);
    const float* yb = y + (size_t)b * 3 * 262144;
    float2 v;
    if (p == 0) v = make_float2(yb[yi*512 + yj], yb[262144 + yi*512 + yj]);
    else        v = make_float2(yb[2*262144 + yi*512 + yj], 0.f);
    g_A[n] = v;
  }
}

// ---------------- FFT pass kernels (128 threads) ------------------------------
__global__ void __launch_bounds__(128) rowfft_fwd() {   // A -> B, fwd rows
  __shared__ float2 s[SPAD];
  int row = blockIdx.x, im = blockIdx.y, tid = threadIdx.x;
  size_t base = ((size_t)im*NPIX + row) * NPIX;
#pragma unroll
  for (int kk = 0; kk < 16; kk++) {
    int n = tid + (kk << 7);
    float2 v = make_float2(0.f, 0.f);
    if (n < NPIX) v = cmul(g_A[base + n], g_Achirp[n]);
    s[PADI(n)] = v;
  }
  conv_core16(s, tid);
#pragma unroll
  for (int kk = 0; kk < 5; kk++) {
    int n = tid + (kk << 7);
    if (n < NPIX) g_B[base + n] = cmul(s[PADI(n)], g_Achirp[n]);
  }
}

// fused: fwd col DFT + OTF multiply + inv col DFT, in-place on B
__global__ void __launch_bounds__(128) colfft_otf() {
  __shared__ float2 s[SPAD];
  int col = blockIdx.x, im = blockIdx.y, tid = threadIdx.x, b = im >> 1;
  size_t base = (size_t)im*NPIX2 + col;
#pragma unroll
  for (int kk = 0; kk < 16; kk++) {
    int n = tid + (kk << 7);
    float2 v = make_float2(0.f, 0.f);
    if (n < NPIX) v = cmul(g_B[base + (size_t)n*NPIX], g_Achirp[n]);
    s[PADI(n)] = v;
  }
  conv_core16(s, tid);
  float2 sp[5];
#pragma unroll
  for (int kk = 0; kk < 5; kk++) {
    int n = tid + (kk << 7);
    if (n < NPIX) {
      float2 S = cmul(s[PADI(n)], g_Achirp[n]);
      sp[kk] = cmul(S, g_Kotf[((size_t)b*NPIX + n)*NPIX + col]);
    }
  }
#pragma unroll
  for (int kk = 0; kk < 16; kk++) {
    int n = tid + (kk << 7);
    float2 v = make_float2(0.f, 0.f);
    if (kk < 5 && n < NPIX) { float2 z = sp[kk]; z.y = -z.y; v = cmul(z, g_Achirp[n]); }
    s[PADI(n)] = v;
  }
  conv_core16(s, tid);
#pragma unroll
  for (int kk = 0; kk < 5; kk++) {
    int n = tid + (kk << 7);
    if (n < NPIX) {
      float2 r = cmul(s[PADI(n)], g_Achirp[n]);
      g_B[base + (size_t)n*NPIX] = make_float2(r.x*INV542, -r.y*INV542);
    }
  }
}

// fused per-iteration row pass: inv row DFT of B + alpha blend into A + fwd row DFT
__global__ void __launch_bounds__(128) row_iter() {
  __shared__ float2 s[SPAD];
  int row = blockIdx.x, im = blockIdx.y, tid = threadIdx.x, b = im >> 1;
  size_t base = ((size_t)im*NPIX + row) * NPIX;
#pragma unroll
  for (int kk = 0; kk < 16; kk++) {
    int n = tid + (kk << 7);
    float2 v = make_float2(0.f, 0.f);
    if (n < NPIX) { float2 z = g_B[base + n]; z.y = -z.y; v = cmul(z, g_Achirp[n]); }
    s[PADI(n)] = v;
  }
  conv_core16(s, tid);
  float v0 = g_v[(b*2+0)*NPIX + row];
  float2 nv[5];
#pragma unroll
  for (int kk = 0; kk < 5; kk++) {
    int n = tid + (kk << 7);
    nv[kk] = make_float2(0.f, 0.f);
    if (n < NPIX) {
      float2 r = cmul(s[PADI(n)], g_Achirp[n]);
      float2 blur = make_float2(r.x*INV542, -r.y*INV542);
      float a = v0 * g_v[(b*2+1)*NPIX + n];
      float2 x = g_A[base + n];
      float2 t = make_float2(a*x.x + (1.f-a)*blur.x, a*x.y + (1.f-a)*blur.y);
      nv[kk] = t;
      g_A[base + n] = t;
    }
  }
#pragma unroll
  for (int kk = 0; kk < 16; kk++) {
    int n = tid + (kk << 7);
    float2 v = make_float2(0.f, 0.f);
    if (kk < 5 && n < NPIX) v = cmul(nv[kk], g_Achirp[n]);
    s[PADI(n)] = v;
  }
  conv_core16(s, tid);
#pragma unroll
  for (int kk = 0; kk < 5; kk++) {
    int n = tid + (kk << 7);
    if (n < NPIX) g_B[base + n] = cmul(s[PADI(n)], g_Achirp[n]);
  }
}

// generic column pass: which=0 -> B, which=1 -> A; inv flag
__global__ void __launch_bounds__(128) colfft_dir(int which, int invdir) {
  __shared__ float2 s[SPAD];
  int col = blockIdx.x, im = blockIdx.y, tid = threadIdx.x;
  float2* buf = which ? g_A : g_B;
  size_t base = (size_t)im*NPIX2 + col;
#pragma unroll
  for (int kk = 0; kk < 16; kk++) {
    int n = tid + (kk << 7);
    float2 v = make_float2(0.f, 0.f);
    if (n < NPIX) {
      float2 z = buf[base + (size_t)n*NPIX];
      if (invdir) z.y = -z.y;
      v = cmul(z, g_Achirp[n]);
    }
    s[PADI(n)] = v;
  }
  conv_core16(s, tid);
#pragma unroll
  for (int kk = 0; kk < 5; kk++) {
    int n = tid + (kk << 7);
    if (n < NPIX) {
      float2 r = cmul(s[PADI(n)], g_Achirp[n]);
      if (invdir) { r.x *= INV542; r.y = -r.y * INV542; }
      buf[base + (size_t)n*NPIX] = r;
    }
  }
}

// Wiener filter in spectrum: read full spectrum from B, write filtered to A.
__global__ void wiener_filter(const float* __restrict__ lam) {
  int u = blockIdx.x, im = blockIdx.y, tid = threadIdx.x;
  int b = im >> 1, p = im & 1;
  float el = expf(lam[0]);
  int mu = (NPIX - u) % NPIX;
  for (int v = tid; v < NPIX; v += blockDim.x) {
    float2 Dk = g_Kotf[((size_t)b*NPIX + u)*NPIX + v];
    float dk2 = Dk.x*Dk.x + Dk.y*Dk.y;
    float2 Dkc = make_float2(Dk.x, -Dk.y);
    size_t idx = (size_t)im*NPIX2 + (size_t)u*NPIX + v;
    float2 Z = g_B[idx];
    float2 Y;
    if (p == 0) {
      int mv = (NPIX - v) % NPIX;
      float2 Zm = g_B[(size_t)im*NPIX2 + (size_t)mu*NPIX + mv];
      float2 F0 = make_float2(0.5f*(Z.x + Zm.x),  0.5f*(Z.y - Zm.y));
      float2 F1 = make_float2(0.5f*(Z.y + Zm.y), -0.5f*(Z.x - Zm.x));
      float om0 = 1.f / (dk2 + el * g_Gsum[(size_t)(0*NPIX + u)*NPIX + v]);
      float om1 = 1.f / (dk2 + el * g_Gsum[(size_t)(1*NPIX + u)*NPIX + v]);
      float2 Y0 = cmul(F0, Dkc); Y0.x *= om0; Y0.y *= om0;
      float2 Y1 = cmul(F1, Dkc); Y1.x *= om1; Y1.y *= om1;
      Y = make_float2(Y0.x - Y1.y, Y0.y + Y1.x);
    } else {
      float om2 = 1.f / (dk2 + el * g_Gsum[(size_t)(2*NPIX + u)*NPIX + v]);
      Y = cmul(Z, Dkc); Y.x *= om2; Y.y *= om2;
    }
    g_A[idx] = Y;
  }
}

// final inverse row DFT of A + unpack channels to output
__global__ void __launch_bounds__(128) row_inv_out(float* __restrict__ out) {
  __shared__ float2 s[SPAD];
  int row = blockIdx.x, im = blockIdx.y, tid = threadIdx.x;
  int b = im >> 1, p = im & 1;
  size_t base = ((size_t)im*NPIX + row) * NPIX;
#pragma unroll
  for (int kk = 0; kk < 16; kk++) {
    int n = tid + (kk << 7);
    float2 v = make_float2(0.f, 0.f);
    if (n < NPIX) { float2 z = g_A[base + n]; z.y = -z.y; v = cmul(z, g_Achirp[n]); }
    s[PADI(n)] = v;
  }
  conv_core16(s, tid);
#pragma unroll
  for (int kk = 0; kk < 5; kk++) {
    int n = tid + (kk << 7);
    if (n < NPIX) {
      float2 r = cmul(s[PADI(n)], g_Achirp[n]);
      float re  =  r.x * INV542;
      float imv = -r.y * INV542;
      if (p == 0) {
        out[(((size_t)b*3 + 0)*NPIX + row)*NPIX + n] = re;
        out[(((size_t)b*3 + 1)*NPIX + row)*NPIX + n] = imv;
      } else {
        out[(((size_t)b*3 + 2)*NPIX + row)*NPIX + n] = re;
      }
    }
  }
}

// ---------------- launch ------------------------------------------------------
extern "C" void kernel_launch(void* const* d_in, const int* in_sizes, int n_in,
                              void* d_out, int out_size) {
  const float* y    = (const float*)d_in[0];
  const float* k    = (const float*)d_in[1];
  const float* lam  = (const float*)d_in[2];
  const float* filt = (const float*)d_in[3];
  float* out = (float*)d_out;

  init_tables<<<8, 256>>>();
  init_bhat<<<1, 128>>>();
  compute_v<<<NBATCH, 32>>>(k);
  kotf_pass1<<<dim3(NPIX, NBATCH), 32>>>(k);
  kotf_pass2<<<dim3(NPIX, NBATCH), 256>>>();
  gsum_kernel<<<dim3(NPIX, 3), 256>>>(filt);
  pad_pack<<<8192, 256>>>(y);

  dim3 fgrid(NPIX, NIMG);
  rowfft_fwd<<<fgrid, 128>>>();
  for (int t = 0; t < 3; t++) {
    colfft_otf<<<fgrid, 128>>>();
    row_iter<<<fgrid, 128>>>();
  }
  colfft_dir<<<fgrid, 128>>>(0, 0);
  wiener_filter<<<fgrid, 256>>>(lam);
  colfft_dir<<<fgrid, 128>>>(1, 1);
  row_inv_out<<<fgrid, 128>>>(out);
}

// round 5
// speedup vs baseline: 3.1652x; 1.0356x over previous
#include <cuda_runtime.h>
#include <math.h>

#define NPIX   542
#define NPIX2  (NPIX*NPIX)
#define NIMG   16
#define M1280  1280
#define T160   160
#define KH     31
#define NF     8
#define NBATCH 8
#define INV542 (1.0f/542.0f)
#define PAD20(i) ((i) + (i)/20)
#define SPAD   1344

// ---------------- scratch (static device globals; no allocation) -------------
__device__ float2 g_A[NIMG*NPIX2];
__device__ float2 g_B[NIMG*NPIX2];
__device__ float2 g_Kotf[NBATCH*NPIX2];
__device__ float  g_Gsum[3*NPIX2];
__device__ float2 g_T[NBATCH*NPIX*KH];
__device__ float  g_v[NBATCH*2*NPIX];
__device__ float2 g_W[M1280];             // W_1280^{-t}
__device__ float2 g_Achirp[NPIX];
__device__ float2 g_E542[NPIX];
__device__ __align__(16) float2 g_Bhat[M1280];  // scrambled FFT(chirp b)/1280

__device__ __forceinline__ float2 cmul(float2 a, float2 b) {
  return make_float2(a.x*b.x - a.y*b.y, a.x*b.y + a.y*b.x);
}
__device__ __forceinline__ float2 cadd(float2 a, float2 b){return make_float2(a.x+b.x,a.y+b.y);}
__device__ __forceinline__ float2 csub(float2 a, float2 b){return make_float2(a.x-b.x,a.y-b.y);}
__device__ __forceinline__ float2 mineg(float2 a){return make_float2(a.y,-a.x);}  // -i*a
__device__ __forceinline__ float2 mipos(float2 a){return make_float2(-a.y,a.x);}  // +i*a

#define SQ8 0.70710678118654752f

// ---------------- radix-8 butterflies (natural order in/out) ------------------
__device__ __forceinline__ void bfly8_fwd(float2* u){
  float2 t0=cadd(u[0],u[4]), t4=csub(u[0],u[4]);
  float2 t1=cadd(u[1],u[5]), t5=csub(u[1],u[5]);
  float2 t2=cadd(u[2],u[6]), t6=mineg(csub(u[2],u[6]));
  float2 t3=cadd(u[3],u[7]), t7=mineg(csub(u[3],u[7]));
  float2 a0=cadd(t0,t2), a1=csub(t0,t2);
  float2 c0=cadd(t1,t3), c1=csub(t1,t3);
  float2 b0=cadd(t4,t6), b1=csub(t4,t6);
  float2 d0=cadd(t5,t7), d1=csub(t5,t7);
  float2 w1d = make_float2(SQ8*(d0.x+d0.y), SQ8*(d0.y-d0.x));
  float2 w3d = make_float2(SQ8*(d1.y-d1.x), -SQ8*(d1.x+d1.y));
  float2 mc1 = mineg(c1);
  u[0]=cadd(a0,c0); u[4]=csub(a0,c0);
  u[2]=cadd(a1,mc1); u[6]=csub(a1,mc1);
  u[1]=cadd(b0,w1d); u[5]=csub(b0,w1d);
  u[3]=cadd(b1,w3d); u[7]=csub(b1,w3d);
}
__device__ __forceinline__ void bfly8_inv(float2* u){
  float2 t0=cadd(u[0],u[4]), t4=csub(u[0],u[4]);
  float2 t1=cadd(u[1],u[5]), t5=csub(u[1],u[5]);
  float2 t2=cadd(u[2],u[6]), t6=mipos(csub(u[2],u[6]));
  float2 t3=cadd(u[3],u[7]), t7=mipos(csub(u[3],u[7]));
  float2 a0=cadd(t0,t2), a1=csub(t0,t2);
  float2 c0=cadd(t1,t3), c1=csub(t1,t3);
  float2 b0=cadd(t4,t6), b1=csub(t4,t6);
  float2 d0=cadd(t5,t7), d1=csub(t5,t7);
  float2 w1d = make_float2(SQ8*(d0.x-d0.y), SQ8*(d0.x+d0.y));
  float2 w3d = make_float2(-SQ8*(d1.x+d1.y), SQ8*(d1.x-d1.y));
  float2 pc1 = mipos(c1);
  u[0]=cadd(a0,c0); u[4]=csub(a0,c0);
  u[2]=cadd(a1,pc1); u[6]=csub(a1,pc1);
  u[1]=cadd(b0,w1d); u[5]=csub(b0,w1d);
  u[3]=cadd(b1,w3d); u[7]=csub(b1,w3d);
}

// ---------------- radix-4 / radix-5 primitives --------------------------------
__device__ __forceinline__ void dft4f(float2&a,float2&b,float2&c,float2&d){
  float2 t0=cadd(a,c), t1=csub(a,c), t2=cadd(b,d), t3=csub(b,d);
  a=cadd(t0,t2); c=csub(t0,t2); b=cadd(t1,mineg(t3)); d=cadd(t1,mipos(t3));
}
__device__ __forceinline__ void dft4i(float2&a,float2&b,float2&c,float2&d){
  float2 t0=cadd(a,c), t1=csub(a,c), t2=cadd(b,d), t3=csub(b,d);
  a=cadd(t0,t2); c=csub(t0,t2); b=cadd(t1,mipos(t3)); d=cadd(t1,mineg(t3));
}
#define C5A 0.30901699437494742f
#define C5B (-0.80901699437494742f)
#define S5A 0.95105651629515357f
#define S5B 0.58778525229247313f
__device__ __forceinline__ void dft5f(float2* x){
  float2 a1=cadd(x[1],x[4]), a2=cadd(x[2],x[3]);
  float2 b1=csub(x[1],x[4]), b2=csub(x[2],x[3]);
  float2 x0=x[0];
  float2 X0=cadd(x0, cadd(a1,a2));
  float2 T1=make_float2(x0.x + C5A*a1.x + C5B*a2.x, x0.y + C5A*a1.y + C5B*a2.y);
  float2 T2=make_float2(x0.x + C5B*a1.x + C5A*a2.x, x0.y + C5B*a1.y + C5A*a2.y);
  float2 S1=make_float2(S5A*b1.x + S5B*b2.x, S5A*b1.y + S5B*b2.y);
  float2 S2=make_float2(S5B*b1.x - S5A*b2.x, S5B*b1.y - S5A*b2.y);
  x[0]=X0;
  x[1]=cadd(T1, mineg(S1)); x[4]=cadd(T1, mipos(S1));
  x[2]=cadd(T2, mineg(S2)); x[3]=cadd(T2, mipos(S2));
}
__device__ __forceinline__ void dft5i(float2* x){
  float2 a1=cadd(x[1],x[4]), a2=cadd(x[2],x[3]);
  float2 b1=csub(x[1],x[4]), b2=csub(x[2],x[3]);
  float2 x0=x[0];
  float2 X0=cadd(x0, cadd(a1,a2));
  float2 T1=make_float2(x0.x + C5A*a1.x + C5B*a2.x, x0.y + C5A*a1.y + C5B*a2.y);
  float2 T2=make_float2(x0.x + C5B*a1.x + C5A*a2.x, x0.y + C5B*a1.y + C5A*a2.y);
  float2 S1=make_float2(S5A*b1.x + S5B*b2.x, S5A*b1.y + S5B*b2.y);
  float2 S2=make_float2(S5B*b1.x - S5A*b2.x, S5B*b1.y - S5A*b2.y);
  x[0]=X0;
  x[1]=cadd(T1, mipos(S1)); x[4]=cadd(T1, mineg(S1));
  x[2]=cadd(T2, mipos(S2)); x[3]=cadd(T2, mineg(S2));
}

// ---------------- pipeline stages ---------------------------------------------
// fwd radix-8 DIF at distance D; twiddle W_{8D}^{ik} = g_W[(i*k)*ST], ST=1280/(8D)
template<int D, int ST>
__device__ __forceinline__ void fwd8s(float2* s, int tid) {
  int i = tid % D;
  int base = (tid / D) * (8*D) + i;
  float2 u[8];
#pragma unroll
  for (int j = 0; j < 8; j++) u[j] = s[PAD20(base + j*D)];
  bfly8_fwd(u);
#pragma unroll
  for (int k = 1; k < 8; k++) u[k] = cmul(u[k], g_W[(i*k)*ST]);
#pragma unroll
  for (int k = 0; k < 8; k++) s[PAD20(base + k*D)] = u[k];
}
template<int D, int ST>
__device__ __forceinline__ void inv8s(float2* s, int tid) {
  int i = tid % D;
  int base = (tid / D) * (8*D) + i;
  float2 u[8];
#pragma unroll
  for (int k = 0; k < 8; k++) {
    float2 z = s[PAD20(base + k*D)];
    if (k) { float2 w = g_W[(i*k)*ST]; z = cmul(z, make_float2(w.x, -w.y)); }
    u[k] = z;
  }
  bfly8_inv(u);
#pragma unroll
  for (int k = 0; k < 8; k++) s[PAD20(base + k*D)] = u[k];
}

// forward DFT-20 on a register block of 20 (radix-4 stage then 4x DFT-5)
__device__ __forceinline__ void fwd20r(float2* x) {
#pragma unroll
  for (int n = 0; n < 5; n++) {
    float2 a=x[n], b=x[n+5], c=x[n+10], d=x[n+15];
    dft4f(a,b,c,d);
    x[n]=a;
    if (n) {
      x[n+5] = cmul(b, g_W[64*n]);
      x[n+10]= cmul(c, g_W[128*n]);
      x[n+15]= cmul(d, g_W[192*n]);
    } else { x[5]=b; x[10]=c; x[15]=d; }
  }
  dft5f(x); dft5f(x+5); dft5f(x+10); dft5f(x+15);
}
__device__ __forceinline__ void inv20r(float2* x) {
  dft5i(x); dft5i(x+5); dft5i(x+10); dft5i(x+15);
#pragma unroll
  for (int n = 0; n < 5; n++) {
    float2 a=x[n], b=x[n+5], c=x[n+10], d=x[n+15];
    if (n) {
      float2 w1=g_W[64*n], w2=g_W[128*n], w3=g_W[192*n];
      b = cmul(b, make_float2(w1.x,-w1.y));
      c = cmul(c, make_float2(w2.x,-w2.y));
      d = cmul(d, make_float2(w3.x,-w3.y));
    }
    dft4i(a,b,c,d);
    x[n]=a; x[n+5]=b; x[n+10]=c; x[n+15]=d;
  }
}

// fused mid: fwd DFT-20 + pointwise scrambled-Bhat + inv DFT-20 (64 threads)
__device__ __forceinline__ void mid20(float2* s, int tid) {
  if (tid < 64) {
    int base = 20*tid;
    float2 x[20];
#pragma unroll
    for (int j = 0; j < 20; j++) x[j] = s[PAD20(base + j)];
    fwd20r(x);
    const float4* bp = (const float4*)(g_Bhat + base);
#pragma unroll
    for (int j = 0; j < 10; j++) {
      float4 bb = bp[j];
      x[2*j]   = cmul(x[2*j],   make_float2(bb.x, bb.y));
      x[2*j+1] = cmul(x[2*j+1], make_float2(bb.z, bb.w));
    }
    inv20r(x);
#pragma unroll
    for (int j = 0; j < 20; j++) s[PAD20(base + j)] = x[j];
  }
}

// circular convolution with chirp b (5 smem round trips, 5 syncs)
__device__ __forceinline__ void conv_core(float2* s, int tid) {
  fwd8s<160,1>(s, tid); __syncthreads();
  fwd8s<20,8>(s, tid);  __syncthreads();
  mid20(s, tid);        __syncthreads();
  inv8s<20,8>(s, tid);  __syncthreads();
  inv8s<160,1>(s, tid); __syncthreads();
}

// forward-only (for building scrambled Bhat; must match data fwd path)
__device__ __forceinline__ void fwd_only(float2* s, int tid) {
  fwd8s<160,1>(s, tid); __syncthreads();
  fwd8s<20,8>(s, tid);  __syncthreads();
  if (tid < 64) {
    int base = 20*tid;
    float2 x[20];
#pragma unroll
    for (int j = 0; j < 20; j++) x[j] = s[PAD20(base + j)];
    fwd20r(x);
#pragma unroll
    for (int j = 0; j < 20; j++) s[PAD20(base + j)] = x[j];
  }
  __syncthreads();
}

// ---------------- table init -------------------------------------------------
__global__ void init_tables() {
  int t = blockIdx.x * blockDim.x + threadIdx.x;
  if (t < M1280) {
    double a = -(2.0 * M_PI / (double)M1280) * (double)t;
    g_W[t] = make_float2((float)cos(a), (float)sin(a));
  }
  if (t < NPIX) {
    long long m = ((long long)t * t) % (2*NPIX);
    double a = -(M_PI / (double)NPIX) * (double)m;
    g_Achirp[t] = make_float2((float)cos(a), (float)sin(a));
    double a2 = -(2.0 * M_PI / (double)NPIX) * (double)t;
    g_E542[t] = make_float2((float)cos(a2), (float)sin(a2));
  }
}

__global__ void __launch_bounds__(T160) init_bhat() {
  __shared__ float2 s[SPAD];
  int tid = threadIdx.x;
#pragma unroll
  for (int kk = 0; kk < 8; kk++) {
    int n = tid + kk*T160;
    float2 v = make_float2(0.f, 0.f);
    if (n < NPIX)            { float2 a = g_Achirp[n];         v = make_float2(a.x, -a.y); }
    else if (n > M1280-NPIX) { float2 a = g_Achirp[M1280 - n]; v = make_float2(a.x, -a.y); }
    s[PAD20(n)] = v;
  }
  __syncthreads();
  fwd_only(s, tid);
#pragma unroll
  for (int kk = 0; kk < 8; kk++) {
    int n = tid + kk*T160;
    float2 z = s[PAD20(n)];
    g_Bhat[n] = make_float2(z.x * (1.f/M1280), z.y * (1.f/M1280));
  }
}

// ---------------- edgetaper alpha windows ------------------------------------
__global__ void compute_v(const float* __restrict__ k) {
  int b = blockIdx.x, tid = threadIdx.x;           // 32 threads
  __shared__ float p0[KH], p1[KH], r0a[KH], r1a[KH];
  if (tid < KH) {
    float s0 = 0.f, s1 = 0.f;
    for (int j = 0; j < KH; j++) {
      s0 += k[b*KH*KH + tid*KH + j];
      s1 += k[b*KH*KH + j*KH + tid];
    }
    p0[tid] = s0; p1[tid] = s1;
  }
  __syncthreads();
  if (tid < KH) {
    float a0 = 0.f, a1 = 0.f;
    for (int m = 0; m + tid < KH; m++) { a0 += p0[m]*p0[m+tid]; a1 += p1[m]*p1[m+tid]; }
    r0a[tid] = a0; r1a[tid] = a1;
  }
  __syncthreads();
  float inv0 = 1.f / r0a[0], inv1 = 1.f / r1a[0];
  for (int n = tid; n < NPIX; n += 32) {
    float z0 = 0.f, z1 = 0.f;
    if (n <= KH-1)                         { z0 = r0a[n];            z1 = r1a[n]; }
    else if (n >= NPIX-KH && n <= NPIX-2)  { z0 = r0a[(NPIX-1) - n]; z1 = r1a[(NPIX-1) - n]; }
    else if (n == NPIX-1)                  { z0 = r0a[0];            z1 = r1a[0]; }
    g_v[(b*2+0)*NPIX + n] = 1.f - z0 * inv0;
    g_v[(b*2+1)*NPIX + n] = 1.f - z1 * inv1;
  }
}

// ---------------- direct-DFT OTFs --------------------------------------------
__global__ void kotf_pass1(const float* __restrict__ k) {
  int u = blockIdx.x, b = blockIdx.y, j = threadIdx.x;
  if (j >= KH) return;
  float2 acc = make_float2(0.f, 0.f);
  for (int i = 0; i < KH; i++) {
    int m = u * (i - 15);
    int idx = m % NPIX; if (idx < 0) idx += NPIX;
    float2 e = g_E542[idx];
    float  w = k[b*KH*KH + i*KH + j];
    acc.x += w*e.x; acc.y += w*e.y;
  }
  g_T[(b*NPIX + u)*KH + j] = acc;
}

__global__ void kotf_pass2() {
  int u = blockIdx.x, b = blockIdx.y, tid = threadIdx.x;
  __shared__ float2 Ts[KH];
  if (tid < KH) Ts[tid] = g_T[(b*NPIX + u)*KH + tid];
  __syncthreads();
  for (int v = tid; v < NPIX; v += blockDim.x) {
    float2 acc = make_float2(0.f, 0.f);
    for (int j = 0; j < KH; j++) {
      int m = v * (j - 15);
      int idx = m % NPIX; if (idx < 0) idx += NPIX;
      float2 e = g_E542[idx], t = Ts[j];
      acc.x += t.x*e.x - t.y*e.y;
      acc.y += t.x*e.y + t.y*e.x;
    }
    g_Kotf[(b*NPIX + u)*NPIX + v] = acc;
  }
}

__global__ void gsum_kernel(const float* __restrict__ filt) {
  int u = blockIdx.x, c = blockIdx.y, tid = threadIdx.x;
  __shared__ float f[NF*9];
  if (tid < NF*9) { int ff = tid/9, t = tid%9; f[tid] = filt[(ff*3 + c)*9 + t]; }
  __syncthreads();
  for (int v = tid; v < NPIX; v += blockDim.x) {
    float sum = 0.f;
    for (int ff = 0; ff < NF; ff++) {
      float ar = 0.f, ai = 0.f;
#pragma unroll
      for (int t = 0; t < 9; t++) {
        int i = t/3, j = t%3;
        int sgn = u*(i-1) + v*(j-1);
        int idx = sgn % NPIX; if (idx < 0) idx += NPIX;
        float2 e = g_E542[idx]; float w = f[ff*9 + t];
        ar += w*e.x; ai += w*e.y;
      }
      sum += ar*ar + ai*ai;
    }
    g_Gsum[(c*NPIX + u)*NPIX + v] = sum;
  }
}

// ---------------- pad (edge replicate) + channel pack ------------------------
__global__ void pad_pack(const float* __restrict__ y) {
  int total = NIMG*NPIX2;
  for (int n = blockIdx.x*blockDim.x + threadIdx.x; n < total; n += gridDim.x*blockDim.x) {
    int im = n / NPIX2, rem = n % NPIX2;
    int i = rem / NPIX, j = rem % NPIX;
    int b = im >> 1, p = im & 1;
    int yi = min(max(i - 15, 0), 511), yj = min(max(j - 15, 0), 511);
    const float* yb = y + (size_t)b * 3 * 262144;
    float2 v;
    if (p == 0) v = make_float2(yb[yi*512 + yj], yb[262144 + yi*512 + yj]);
    else        v = make_float2(yb[2*262144 + yi*512 + yj], 0.f);
    g_A[n] = v;
  }
}

// ---------------- FFT pass kernels (160 threads) -------------------------------
__global__ void __launch_bounds__(T160) rowfft_fwd() {   // A -> B, fwd rows
  __shared__ float2 s[SPAD];
  int row = blockIdx.x, im = blockIdx.y, tid = threadIdx.x;
  size_t base = ((size_t)im*NPIX + row) * NPIX;
#pragma unroll
  for (int kk = 0; kk < 8; kk++) {
    int n = tid + kk*T160;
    float2 v = make_float2(0.f, 0.f);
    if (n < NPIX) v = cmul(g_A[base + n], g_Achirp[n]);
    s[PAD20(n)] = v;
  }
  __syncthreads();
  conv_core(s, tid);
#pragma unroll
  for (int kk = 0; kk < 4; kk++) {
    int n = tid + kk*T160;
    if (n < NPIX) g_B[base + n] = cmul(s[PAD20(n)], g_Achirp[n]);
  }
}

// fused: fwd col DFT + OTF multiply + inv col DFT, in-place on B
__global__ void __launch_bounds__(T160) colfft_otf() {
  __shared__ float2 s[SPAD];
  int col = blockIdx.x, im = blockIdx.y, tid = threadIdx.x, b = im >> 1;
  size_t base = (size_t)im*NPIX2 + col;
#pragma unroll
  for (int kk = 0; kk < 8; kk++) {
    int n = tid + kk*T160;
    float2 v = make_float2(0.f, 0.f);
    if (n < NPIX) v = cmul(g_B[base + (size_t)n*NPIX], g_Achirp[n]);
    s[PAD20(n)] = v;
  }
  __syncthreads();
  conv_core(s, tid);
  float2 sp[4];
#pragma unroll
  for (int kk = 0; kk < 4; kk++) {
    int n = tid + kk*T160;
    if (n < NPIX) {
      float2 S = cmul(s[PAD20(n)], g_Achirp[n]);
      sp[kk] = cmul(S, g_Kotf[((size_t)b*NPIX + n)*NPIX + col]);
    }
  }
  __syncthreads();
#pragma unroll
  for (int kk = 0; kk < 8; kk++) {
    int n = tid + kk*T160;
    float2 v = make_float2(0.f, 0.f);
    if (kk < 4 && n < NPIX) { float2 z = sp[kk]; z.y = -z.y; v = cmul(z, g_Achirp[n]); }
    s[PAD20(n)] = v;
  }
  __syncthreads();
  conv_core(s, tid);
#pragma unroll
  for (int kk = 0; kk < 4; kk++) {
    int n = tid + kk*T160;
    if (n < NPIX) {
      float2 r = cmul(s[PAD20(n)], g_Achirp[n]);
      g_B[base + (size_t)n*NPIX] = make_float2(r.x*INV542, -r.y*INV542);
    }
  }
}

// fused per-iteration row pass: inv row DFT of B + alpha blend into A + fwd row DFT
__global__ void __launch_bounds__(T160) row_iter() {
  __shared__ float2 s[SPAD];
  int row = blockIdx.x, im = blockIdx.y, tid = threadIdx.x, b = im >> 1;
  size_t base = ((size_t)im*NPIX + row) * NPIX;
#pragma unroll
  for (int kk = 0; kk < 8; kk++) {
    int n = tid + kk*T160;
    float2 v = make_float2(0.f, 0.f);
    if (n < NPIX) { float2 z = g_B[base + n]; z.y = -z.y; v = cmul(z, g_Achirp[n]); }
    s[PAD20(n)] = v;
  }
  __syncthreads();
  conv_core(s, tid);
  float v0 = g_v[(b*2+0)*NPIX + row];
  float2 nv[4];
#pragma unroll
  for (int kk = 0; kk < 4; kk++) {
    int n = tid + kk*T160;
    nv[kk] = make_float2(0.f, 0.f);
    if (n < NPIX) {
      float2 r = cmul(s[PAD20(n)], g_Achirp[n]);
      float2 blur = make_float2(r.x*INV542, -r.y*INV542);
      float a = v0 * g_v[(b*2+1)*NPIX + n];
      float2 x = g_A[base + n];
      float2 t = make_float2(a*x.x + (1.f-a)*blur.x, a*x.y + (1.f-a)*blur.y);
      nv[kk] = t;
      g_A[base + n] = t;
    }
  }
  __syncthreads();
#pragma unroll
  for (int kk = 0; kk < 8; kk++) {
    int n = tid + kk*T160;
    float2 v = make_float2(0.f, 0.f);
    if (kk < 4 && n < NPIX) v = cmul(nv[kk], g_Achirp[n]);
    s[PAD20(n)] = v;
  }
  __syncthreads();
  conv_core(s, tid);
#pragma unroll
  for (int kk = 0; kk < 4; kk++) {
    int n = tid + kk*T160;
    if (n < NPIX) g_B[base + n] = cmul(s[PAD20(n)], g_Achirp[n]);
  }
}

// generic column pass: which=0 -> B, which=1 -> A; inv flag
__global__ void __launch_bounds__(T160) colfft_dir(int which, int invdir) {
  __shared__ float2 s[SPAD];
  int col = blockIdx.x, im = blockIdx.y, tid = threadIdx.x;
  float2* buf = which ? g_A : g_B;
  size_t base = (size_t)im*NPIX2 + col;
#pragma unroll
  for (int kk = 0; kk < 8; kk++) {
    int n = tid + kk*T160;
    float2 v = make_float2(0.f, 0.f);
    if (n < NPIX) {
      float2 z = buf[base + (size_t)n*NPIX];
      if (invdir) z.y = -z.y;
      v = cmul(z, g_Achirp[n]);
    }
    s[PAD20(n)] = v;
  }
  __syncthreads();
  conv_core(s, tid);
#pragma unroll
  for (int kk = 0; kk < 4; kk++) {
    int n = tid + kk*T160;
    if (n < NPIX) {
      float2 r = cmul(s[PAD20(n)], g_Achirp[n]);
      if (invdir) { r.x *= INV542; r.y = -r.y * INV542; }
      buf[base + (size_t)n*NPIX] = r;
    }
  }
}

// Wiener filter in spectrum: read full spectrum from B, write filtered to A.
__global__ void wiener_filter(const float* __restrict__ lam) {
  int u = blockIdx.x, im = blockIdx.y, tid = threadIdx.x;
  int b = im >> 1, p = im & 1;
  float el = expf(lam[0]);
  int mu = (NPIX - u) % NPIX;
  for (int v = tid; v < NPIX; v += blockDim.x) {
    float2 Dk = g_Kotf[((size_t)b*NPIX + u)*NPIX + v];
    float dk2 = Dk.x*Dk.x + Dk.y*Dk.y;
    float2 Dkc = make_float2(Dk.x, -Dk.y);
    size_t idx = (size_t)im*NPIX2 + (size_t)u*NPIX + v;
    float2 Z = g_B[idx];
    float2 Y;
    if (p == 0) {
      int mv = (NPIX - v) % NPIX;
      float2 Zm = g_B[(size_t)im*NPIX2 + (size_t)mu*NPIX + mv];
      float2 F0 = make_float2(0.5f*(Z.x + Zm.x),  0.5f*(Z.y - Zm.y));
      float2 F1 = make_float2(0.5f*(Z.y + Zm.y), -0.5f*(Z.x - Zm.x));
      float om0 = 1.f / (dk2 + el * g_Gsum[(size_t)(0*NPIX + u)*NPIX + v]);
      float om1 = 1.f / (dk2 + el * g_Gsum[(size_t)(1*NPIX + u)*NPIX + v]);
      float2 Y0 = cmul(F0, Dkc); Y0.x *= om0; Y0.y *= om0;
      float2 Y1 = cmul(F1, Dkc); Y1.x *= om1; Y1.y *= om1;
      Y = make_float2(Y0.x - Y1.y, Y0.y + Y1.x);
    } else {
      float om2 = 1.f / (dk2 + el * g_Gsum[(size_t)(2*NPIX + u)*NPIX + v]);
      Y = cmul(Z, Dkc); Y.x *= om2; Y.y *= om2;
    }
    g_A[idx] = Y;
  }
}

// final inverse row DFT of A + unpack channels to output
__global__ void __launch_bounds__(T160) row_inv_out(float* __restrict__ out) {
  __shared__ float2 s[SPAD];
  int row = blockIdx.x, im = blockIdx.y, tid = threadIdx.x;
  int b = im >> 1, p = im & 1;
  size_t base = ((size_t)im*NPIX + row) * NPIX;
#pragma unroll
  for (int kk = 0; kk < 8; kk++) {
    int n = tid + kk*T160;
    float2 v = make_float2(0.f, 0.f);
    if (n < NPIX) { float2 z = g_A[base + n]; z.y = -z.y; v = cmul(z, g_Achirp[n]); }
    s[PAD20(n)] = v;
  }
  __syncthreads();
  conv_core(s, tid);
#pragma unroll
  for (int kk = 0; kk < 4; kk++) {
    int n = tid + kk*T160;
    if (n < NPIX) {
      float2 r = cmul(s[PAD20(n)], g_Achirp[n]);
      float re  =  r.x * INV542;
      float imv = -r.y * INV542;
      if (p == 0) {
        out[(((size_t)b*3 + 0)*NPIX + row)*NPIX + n] = re;
        out[(((size_t)b*3 + 1)*NPIX + row)*NPIX + n] = imv;
      } else {
        out[(((size_t)b*3 + 2)*NPIX + row)*NPIX + n] = re;
      }
    }
  }
}

// ---------------- launch ------------------------------------------------------
extern "C" void kernel_launch(void* const* d_in, const int* in_sizes, int n_in,
                              void* d_out, int out_size) {
  const float* y    = (const float*)d_in[0];
  const float* k    = (const float*)d_in[1];
  const float* lam  = (const float*)d_in[2];
  const float* filt = (const float*)d_in[3];
  float* out = (float*)d_out;

  init_tables<<<8, 256>>>();
  init_bhat<<<1, T160>>>();
  compute_v<<<NBATCH, 32>>>(k);
  kotf_pass1<<<dim3(NPIX, NBATCH), 32>>>(k);
  kotf_pass2<<<dim3(NPIX, NBATCH), 256>>>();
  gsum_kernel<<<dim3(NPIX, 3), 256>>>(filt);
  pad_pack<<<8192, 256>>>(y);

  dim3 fgrid(NPIX, NIMG);
  rowfft_fwd<<<fgrid, T160>>>();
  for (int t = 0; t < 3; t++) {
    colfft_otf<<<fgrid, T160>>>();
    row_iter<<<fgrid, T160>>>();
  }
  colfft_dir<<<fgrid, T160>>>(0, 0);
  wiener_filter<<<fgrid, 256>>>(lam);
  colfft_dir<<<fgrid, T160>>>(1, 1);
  row_inv_out<<<fgrid, T160>>>(out);
}